// round 1
// baseline (speedup 1.0000x reference)
#include <cuda_runtime.h>
#include <math.h>

// Problem constants
#define BB 4
#define SS 1024
#define DIM 2048
#define HH 32
#define HD 64
#define RR 16
#define MM (BB*SS)   // 4096

// ---------------- scratch (device globals; no allocation allowed) ----------------
__device__ float g_weff[4][DIM*DIM];     // folded W+L2@L1 for q,k,v,o
__device__ float g_xq[MM*DIM];
__device__ float g_xk[MM*DIM];
__device__ float g_xv[MM*DIM];
__device__ float g_qr[MM*DIM];
__device__ float g_kr[MM*DIM];
__device__ float g_meml[BB*HH*HD*HD];
__device__ float g_memq[BB*HH*HD*HD];
__device__ float g_nrmt[BB*HH*HD];
__device__ float g_comb[MM*DIM];         // g*mem_comb, then += (1-g)*attn

__device__ __forceinline__ float elu1f(float x){ return x > 0.f ? x + 1.f : expf(x); }
__device__ __forceinline__ float sigmf(float x){ return 1.f/(1.f+expf(-x)); }

// ---------------- 1) fold LoRA into dense weights ----------------
// W_eff[n,k] = W[n,k] + sum_r l2[n,r]*l1[r,k]
__global__ void fold_weight_kernel(const float* __restrict__ w,
                                   const float* __restrict__ l1,
                                   const float* __restrict__ l2,
                                   int out_idx)
{
    int i = blockIdx.x * 256 + threadIdx.x;      // 0 .. DIM*DIM-1
    int row = i >> 11;
    int col = i & (DIM - 1);
    float acc = w[i];
#pragma unroll
    for (int r = 0; r < RR; r++)
        acc += l2[row*RR + r] * l1[r*DIM + col];
    g_weff[out_idx][i] = acc;
}

// ---------------- 2) SGEMM: Y(M,N) = X(M,K) @ W(N,K)^T  (all row-major) ----------
// 128x128 tile, K-tile 8, 256 threads, 8x8 micro-tile per thread.
__global__ __launch_bounds__(256, 2)
void sgemm_kernel(const float* __restrict__ Xext, int xsel, int widx,
                  float* __restrict__ Yext, int ysel)
{
    const float* X = xsel ? g_comb : Xext;
    const float* W = g_weff[widx];
    float* Y = (ysel == 0) ? g_xq : (ysel == 1) ? g_xk : (ysel == 2) ? g_xv : Yext;

    __shared__ float As[8*128];
    __shared__ float Bs[8*128];

    int t  = threadIdx.x;
    int m0 = blockIdx.y * 128;
    int n0 = blockIdx.x * 128;
    int ty = t >> 4, tx = t & 15;
    int lrow = t >> 1;            // 0..127
    int lk   = (t & 1) * 4;       // 0 or 4

    float acc[8][8];
#pragma unroll
    for (int i = 0; i < 8; i++)
#pragma unroll
        for (int j = 0; j < 8; j++) acc[i][j] = 0.f;

    const float* xp = X + (size_t)(m0 + lrow) * DIM + lk;
    const float* wp = W + (size_t)(n0 + lrow) * DIM + lk;

    for (int k0 = 0; k0 < DIM; k0 += 8) {
        float4 av = *(const float4*)(xp + k0);
        float4 bv = *(const float4*)(wp + k0);
        __syncthreads();
        As[(lk+0)*128 + lrow] = av.x;
        As[(lk+1)*128 + lrow] = av.y;
        As[(lk+2)*128 + lrow] = av.z;
        As[(lk+3)*128 + lrow] = av.w;
        Bs[(lk+0)*128 + lrow] = bv.x;
        Bs[(lk+1)*128 + lrow] = bv.y;
        Bs[(lk+2)*128 + lrow] = bv.z;
        Bs[(lk+3)*128 + lrow] = bv.w;
        __syncthreads();
#pragma unroll
        for (int kk = 0; kk < 8; kk++) {
            float a[8], b[8];
#pragma unroll
            for (int i = 0; i < 8; i++) a[i] = As[kk*128 + ty + 16*i];
#pragma unroll
            for (int j = 0; j < 8; j++) b[j] = Bs[kk*128 + tx + 16*j];
#pragma unroll
            for (int i = 0; i < 8; i++)
#pragma unroll
                for (int j = 0; j < 8; j++)
                    acc[i][j] += a[i] * b[j];
        }
    }
#pragma unroll
    for (int i = 0; i < 8; i++)
#pragma unroll
        for (int j = 0; j < 8; j++)
            Y[(size_t)(m0 + ty + 16*i) * DIM + (n0 + tx + 16*j)] = acc[i][j];
}

// ---------------- 3) memory-branch statistics per (b,h) ----------------
// mem_l = memory_long + sigma_k^T @ V ; mem_q = memory_query + sigma_k^T @ (V*sig)
// nrm_t = norm_term + sum_s sigma_k
__global__ __launch_bounds__(256)
void mem_stats_kernel(const float* __restrict__ cache_k,
                      const float* __restrict__ cache_v,
                      const float* __restrict__ pquery,
                      const float* __restrict__ meml_in,
                      const float* __restrict__ memq_in,
                      const float* __restrict__ nrm_in)
{
    int bh = blockIdx.x;
    int b = bh >> 5, h = bh & 31;
    __shared__ float Ks[32][64];
    __shared__ float Vs[32][64];
    __shared__ float pqs[64];
    __shared__ float sig[32];

    int t = threadIdx.x;
    if (t < 64) pqs[t] = pquery[(b*HH + h)*HD + t];

    float accl[4][4] = {{0}}, accq[4][4] = {{0}};
    float accn = 0.f;
    int lrow = t >> 3;            // 0..31
    int lcol = (t & 7) * 8;       // 0..56
    int d0 = (t >> 4) * 4;
    int e0 = (t & 15) * 4;

    for (int s0 = 0; s0 < SS; s0 += 32) {
        __syncthreads();
        const float* kp = cache_k + ((size_t)((b*SS + s0 + lrow)*HH + h))*HD + lcol;
        const float* vp = cache_v + ((size_t)((b*SS + s0 + lrow)*HH + h))*HD + lcol;
        *(float4*)&Ks[lrow][lcol]   = *(const float4*)kp;
        *(float4*)&Ks[lrow][lcol+4] = *(const float4*)(kp + 4);
        *(float4*)&Vs[lrow][lcol]   = *(const float4*)vp;
        *(float4*)&Vs[lrow][lcol+4] = *(const float4*)(vp + 4);
        __syncthreads();
        if (t < 32) {
            float sum = 0.f;
#pragma unroll
            for (int d = 0; d < 64; d++) sum += pqs[d] * Ks[t][d];
            sig[t] = sigmf(sum * 0.125f);
        }
        __syncthreads();
#pragma unroll
        for (int u = 0; u < 8; u++) Ks[lrow][lcol+u] = elu1f(Ks[lrow][lcol+u]);
        __syncthreads();
        if (t < 64) {
#pragma unroll
            for (int s = 0; s < 32; s++) accn += Ks[s][t];
        }
#pragma unroll 4
        for (int s = 0; s < 32; s++) {
            float4 k4 = *(const float4*)&Ks[s][d0];
            float4 v4 = *(const float4*)&Vs[s][e0];
            float sg = sig[s];
            float ka[4] = {k4.x, k4.y, k4.z, k4.w};
            float kb[4] = {k4.x*sg, k4.y*sg, k4.z*sg, k4.w*sg};
            float vv[4] = {v4.x, v4.y, v4.z, v4.w};
#pragma unroll
            for (int i = 0; i < 4; i++)
#pragma unroll
                for (int j = 0; j < 4; j++) {
                    accl[i][j] += ka[i] * vv[j];
                    accq[i][j] += kb[i] * vv[j];
                }
        }
    }
    size_t base = (size_t)bh * HD * HD;
#pragma unroll
    for (int i = 0; i < 4; i++)
#pragma unroll
        for (int j = 0; j < 4; j++) {
            size_t idx = base + (size_t)(d0 + i)*HD + (e0 + j);
            g_meml[idx] = meml_in[idx] + accl[i][j];
            g_memq[idx] = memq_in[idx] + accq[i][j];
        }
    if (t < 64) g_nrmt[bh*HD + t] = nrm_in[bh*HD + t] + accn;
}

// ---------------- 4) memory-branch apply: g * mem_comb -> g_comb ----------------
__global__ __launch_bounds__(256)
void mem_apply_kernel(const float* __restrict__ gmem_w,
                      const float* __restrict__ gmem_b,
                      const float* __restrict__ gate)
{
    int idx = blockIdx.x;
    int st = idx & 31;          // s-tile (32 rows)
    int h  = (idx >> 5) & 31;
    int b  = idx >> 10;
    int bh = b*HH + h;
    int s0 = st * 32;

    __shared__ float ml[64*64];
    __shared__ float mq[64*64];
    __shared__ float sq[32*68];
    __shared__ float nrm[64];
    __shared__ float wv[64];
    __shared__ float gpart[32*8];

    int t = threadIdx.x;
    // load mem_l / mem_q (16 floats each per thread)
    {
        int r = t >> 2, c = (t & 3) * 16;
        size_t gbase = (size_t)bh*HD*HD + (size_t)r*HD + c;
#pragma unroll
        for (int u = 0; u < 4; u++) {
            *(float4*)&ml[r*64 + c + 4*u] = *(const float4*)&g_meml[gbase + 4*u];
            *(float4*)&mq[r*64 + c + 4*u] = *(const float4*)&g_memq[gbase + 4*u];
        }
    }
    // load sigma_q tile (32 x 64, padded rows)
    {
        int r = t >> 3, c = (t & 7) * 8;
        const float* xp = g_xq + ((size_t)((b*SS + s0 + r)*HH + h))*HD + c;
        float4 a = *(const float4*)xp;
        float4 bv = *(const float4*)(xp + 4);
        float4 ea = make_float4(elu1f(a.x), elu1f(a.y), elu1f(a.z), elu1f(a.w));
        float4 eb = make_float4(elu1f(bv.x), elu1f(bv.y), elu1f(bv.z), elu1f(bv.w));
        *(float4*)&sq[r*68 + c]     = ea;
        *(float4*)&sq[r*68 + c + 4] = eb;
    }
    if (t < 64) { nrm[t] = g_nrmt[bh*HD + t]; wv[t] = gmem_w[t]; }
    __syncthreads();

    int row = t >> 3;           // 0..31
    int eq  = t & 7;            // 0..7 ; e = eq*4 + 32*c + u
    float denom = 0.f;
#pragma unroll
    for (int d = 0; d < 64; d++) denom += sq[row*68 + d] * nrm[d];

    float4 mo[2]  = {make_float4(0,0,0,0), make_float4(0,0,0,0)};
    float4 qmo[2] = {make_float4(0,0,0,0), make_float4(0,0,0,0)};
#pragma unroll
    for (int d = 0; d < 64; d++) {
        float sd = sq[row*68 + d];
#pragma unroll
        for (int c = 0; c < 2; c++) {
            float4 m4 = *(const float4*)&ml[d*64 + eq*4 + 32*c];
            float4 q4 = *(const float4*)&mq[d*64 + eq*4 + 32*c];
            mo[c].x += sd*m4.x; mo[c].y += sd*m4.y; mo[c].z += sd*m4.z; mo[c].w += sd*m4.w;
            qmo[c].x += sd*q4.x; qmo[c].y += sd*q4.y; qmo[c].z += sd*q4.z; qmo[c].w += sd*q4.w;
        }
    }
    float inv = 1.f / denom;
    float gp = 0.f;
#pragma unroll
    for (int c = 0; c < 2; c++) {
        mo[c].x *= inv; mo[c].y *= inv; mo[c].z *= inv; mo[c].w *= inv;
        qmo[c].x *= inv; qmo[c].y *= inv; qmo[c].z *= inv; qmo[c].w *= inv;
        int e = eq*4 + 32*c;
        gp += qmo[c].x*wv[e] + qmo[c].y*wv[e+1] + qmo[c].z*wv[e+2] + qmo[c].w*wv[e+3];
    }
    gpart[row*8 + eq] = gp;
    __syncthreads();
    float gsum = 0.f;
#pragma unroll
    for (int i = 0; i < 8; i++) gsum += gpart[row*8 + i];
    float gq = sigmf(gsum + gmem_b[0]);
    float gh = sigmf(gate[h]);

    float* op = g_comb + ((size_t)((b*SS + s0 + row)*HH + h))*HD;
#pragma unroll
    for (int c = 0; c < 2; c++) {
        float4 o;
        o.x = gh * (mo[c].x + gq*qmo[c].x);
        o.y = gh * (mo[c].y + gq*qmo[c].y);
        o.z = gh * (mo[c].z + gq*qmo[c].z);
        o.w = gh * (mo[c].w + gq*qmo[c].w);
        *(float4*)(op + eq*4 + 32*c) = o;
    }
}

// ---------------- 5) RoPE for q and k ----------------
__global__ void rope_kernel(const float* __restrict__ fc, const float* __restrict__ fs)
{
    int idx = blockIdx.x * 256 + threadIdx.x;    // (b,s,h,i) flat, i < 32
    int i = idx & 31;
    int s = (idx >> 10) & 1023;
    size_t pos = (size_t)idx * 2;
    float c = fc[s*32 + i];
    float sn = fs[s*32 + i];
    float a = g_xq[pos], b2 = g_xq[pos+1];
    g_qr[pos]   = a*c - b2*sn;
    g_qr[pos+1] = a*sn + b2*c;
    a = g_xk[pos]; b2 = g_xk[pos+1];
    g_kr[pos]   = a*c - b2*sn;
    g_kr[pos+1] = a*sn + b2*c;
}

// ---------------- 6) causal flash attention + combine ----------------
// grid: b(4) x h(32) x qtile(16); 256 threads; 64x64 tiles, fp32.
__global__ __launch_bounds__(256, 1)
void flash_kernel(const float* __restrict__ gate)
{
    extern __shared__ float sm[];
    float* Ks   = sm;                 // 64*68
    float* Vs   = Ks + 64*68;
    float* Ps   = Vs + 64*68;
    float* rmax = Ps + 64*68;         // 64*4
    float* rsum = rmax + 256;         // 64*4

    int t  = threadIdx.x;
    int qt = blockIdx.x & 15;
    int h  = (blockIdx.x >> 4) & 31;
    int b  = blockIdx.x >> 9;
    int row = t >> 2;                 // 0..63
    int eq  = t & 3;
    int qglob = qt*64 + row;

    // q row in registers, pre-scaled by 1/sqrt(HD)
    float4 qv[16];
    const float* qp = g_qr + ((size_t)((b*SS + qglob)*HH + h))*HD;
#pragma unroll
    for (int u = 0; u < 16; u++) {
        float4 v = *(const float4*)(qp + 4*u);
        v.x *= 0.125f; v.y *= 0.125f; v.z *= 0.125f; v.w *= 0.125f;
        qv[u] = v;
    }

    float m = -INFINITY, l = 0.f;
    float4 O[4] = {make_float4(0,0,0,0), make_float4(0,0,0,0),
                   make_float4(0,0,0,0), make_float4(0,0,0,0)};

    for (int kt = 0; kt <= qt; kt++) {
        __syncthreads();
        {   // load K/V tiles: thread loads 16 floats of each
            const float* kp = g_kr + ((size_t)((b*SS + kt*64 + row)*HH + h))*HD + eq*16;
            const float* vp = g_xv + ((size_t)((b*SS + kt*64 + row)*HH + h))*HD + eq*16;
#pragma unroll
            for (int u = 0; u < 4; u++) {
                *(float4*)&Ks[row*68 + eq*16 + 4*u] = *(const float4*)(kp + 4*u);
                *(float4*)&Vs[row*68 + eq*16 + 4*u] = *(const float4*)(vp + 4*u);
            }
        }
        __syncthreads();

        // scores for 16 key columns kc = eq*16 + j
        float lmax = -INFINITY;
#pragma unroll
        for (int j = 0; j < 16; j++) {
            int kc = eq*16 + j;
            float sv = 0.f;
#pragma unroll
            for (int u = 0; u < 16; u++) {
                float4 k4 = *(const float4*)&Ks[kc*68 + 4*u];
                sv += qv[u].x*k4.x + qv[u].y*k4.y + qv[u].z*k4.z + qv[u].w*k4.w;
            }
            if (kt == qt && kc > row) sv = -INFINITY;
            Ps[row*68 + kc] = sv;
            lmax = fmaxf(lmax, sv);
        }
        rmax[row*4 + eq] = lmax;
        __syncthreads();
        float tmax = fmaxf(fmaxf(rmax[row*4+0], rmax[row*4+1]),
                           fmaxf(rmax[row*4+2], rmax[row*4+3]));
        float mnew = fmaxf(m, tmax);
        float corr = expf(m - mnew);
        float lsum = 0.f;
#pragma unroll
        for (int j = 0; j < 16; j++) {
            int kc = eq*16 + j;
            float p = expf(Ps[row*68 + kc] - mnew);
            Ps[row*68 + kc] = p;
            lsum += p;
        }
        rsum[row*4 + eq] = lsum;
        __syncthreads();
        float tsum = rsum[row*4+0] + rsum[row*4+1] + rsum[row*4+2] + rsum[row*4+3];
        l = l * corr + tsum;
        m = mnew;
#pragma unroll
        for (int c = 0; c < 4; c++) {
            O[c].x *= corr; O[c].y *= corr; O[c].z *= corr; O[c].w *= corr;
        }
#pragma unroll 8
        for (int kc = 0; kc < 64; kc++) {
            float p = Ps[row*68 + kc];
#pragma unroll
            for (int c = 0; c < 4; c++) {
                float4 v4 = *(const float4*)&Vs[kc*68 + eq*4 + 16*c];
                O[c].x += p*v4.x; O[c].y += p*v4.y; O[c].z += p*v4.z; O[c].w += p*v4.w;
            }
        }
    }

    float gh = sigmf(gate[h]);
    float w1 = (1.f - gh) / l;
    float* op = g_comb + ((size_t)((b*SS + qglob)*HH + h))*HD;
#pragma unroll
    for (int c = 0; c < 4; c++) {
        int e = eq*4 + 16*c;
        float4 prev = *(const float4*)(op + e);
        float4 o;
        o.x = prev.x + w1*O[c].x;
        o.y = prev.y + w1*O[c].y;
        o.z = prev.z + w1*O[c].z;
        o.w = prev.w + w1*O[c].w;
        *(float4*)(op + e) = o;
    }
}

// ---------------- launcher ----------------
extern "C" void kernel_launch(void* const* d_in, const int* in_sizes, int n_in,
                              void* d_out, int out_size)
{
    const float* x     = (const float*)d_in[0];
    const float* pq    = (const float*)d_in[1];
    const float* ck    = (const float*)d_in[2];
    const float* cv    = (const float*)d_in[3];
    const float* meml  = (const float*)d_in[4];
    const float* memq  = (const float*)d_in[5];
    const float* nrm   = (const float*)d_in[6];
    const float* fc    = (const float*)d_in[7];
    const float* fs    = (const float*)d_in[8];
    // d_in[9] = mask (unused: strict causal implemented directly)
    const float* wq    = (const float*)d_in[10];
    const float* wk    = (const float*)d_in[11];
    const float* wv    = (const float*)d_in[12];
    const float* wo    = (const float*)d_in[13];
    const float* lq1   = (const float*)d_in[14];
    const float* lq2   = (const float*)d_in[15];
    const float* lk1   = (const float*)d_in[16];
    const float* lk2   = (const float*)d_in[17];
    const float* lv1   = (const float*)d_in[18];
    const float* lv2   = (const float*)d_in[19];
    const float* lo1   = (const float*)d_in[20];
    const float* lo2   = (const float*)d_in[21];
    const float* gate  = (const float*)d_in[22];
    const float* gw    = (const float*)d_in[23];
    const float* gb    = (const float*)d_in[24];
    // d_in[25] = start_pos (unused; freqs already offset)
    float* out = (float*)d_out;

    const int FOLD_BLOCKS = (DIM*DIM)/256;
    fold_weight_kernel<<<FOLD_BLOCKS, 256>>>(wq, lq1, lq2, 0);
    fold_weight_kernel<<<FOLD_BLOCKS, 256>>>(wk, lk1, lk2, 1);
    fold_weight_kernel<<<FOLD_BLOCKS, 256>>>(wv, lv1, lv2, 2);
    fold_weight_kernel<<<FOLD_BLOCKS, 256>>>(wo, lo1, lo2, 3);

    dim3 gg(DIM/128, MM/128);
    sgemm_kernel<<<gg, 256>>>(x, 0, 0, nullptr, 0);   // xq
    sgemm_kernel<<<gg, 256>>>(x, 0, 1, nullptr, 1);   // xk
    sgemm_kernel<<<gg, 256>>>(x, 0, 2, nullptr, 2);   // xv

    mem_stats_kernel<<<BB*HH, 256>>>(ck, cv, pq, meml, memq, nrm);
    mem_apply_kernel<<<BB*HH*(SS/32), 256>>>(gw, gb, gate);

    rope_kernel<<<(BB*SS*HH*32)/256, 256>>>(fc, fs);

    size_t fl_smem = (size_t)(3*64*68 + 512) * sizeof(float);   // ~54 KB
    cudaFuncSetAttribute(flash_kernel, cudaFuncAttributeMaxDynamicSharedMemorySize,
                         (int)fl_smem);
    flash_kernel<<<BB*HH*(SS/64), 256, fl_smem>>>(gate);

    sgemm_kernel<<<gg, 256>>>(nullptr, 1, 3, out, 3); // final projection
    (void)in_sizes; (void)n_in; (void)out_size;
}

// round 3
// speedup vs baseline: 1.4850x; 1.4850x over previous
#include <cuda_runtime.h>
#include <cuda_fp16.h>
#include <math.h>
#include <stdint.h>

// Problem constants
#define BB 4
#define SS 1024
#define DIM 2048
#define HH 32
#define HD 64
#define RR 16
#define MM (BB*SS)   // 4096

// ---------------- scratch (device globals; no allocation allowed) ----------------
__device__ __half g_whi[4][DIM*DIM];
__device__ __half g_wlo[4][DIM*DIM];
__device__ __half g_xhi[MM*DIM];
__device__ __half g_xlo[MM*DIM];
__device__ float g_xq[MM*DIM];
__device__ float g_xk[MM*DIM];
__device__ float g_xv[MM*DIM];
__device__ float g_qr[MM*DIM];
__device__ float g_kr[MM*DIM];
__device__ float g_meml[BB*HH*HD*HD];
__device__ float g_memq[BB*HH*HD*HD];
__device__ float g_nrmt[BB*HH*HD];
__device__ float g_comb[MM*DIM];

__device__ __forceinline__ float elu1f(float x){ return x > 0.f ? x + 1.f : __expf(x); }
__device__ __forceinline__ float sigmf(float x){ return 1.f/(1.f+__expf(-x)); }

__device__ __forceinline__ uint32_t smem_u32(const void* p){
    uint32_t a;
    asm("{ .reg .u64 t; cvta.to.shared.u64 t, %1; cvt.u32.u64 %0, t; }" : "=r"(a) : "l"(p));
    return a;
}

// ---------------- fp16 hi/lo split of 8 floats -> 2 uint4 ----------------
__device__ __forceinline__ void split8h(const float* v, uint4& hi, uint4& lo){
    unsigned h[4], l[4];
#pragma unroll
    for (int p = 0; p < 4; p++){
        __half h0 = __float2half_rn(v[2*p]);
        __half h1 = __float2half_rn(v[2*p+1]);
        __half l0 = __float2half_rn(v[2*p]   - __half2float(h0));
        __half l1 = __float2half_rn(v[2*p+1] - __half2float(h1));
        h[p] = (unsigned)__half_as_ushort(h0) | ((unsigned)__half_as_ushort(h1) << 16);
        l[p] = (unsigned)__half_as_ushort(l0) | ((unsigned)__half_as_ushort(l1) << 16);
    }
    hi = make_uint4(h[0], h[1], h[2], h[3]);
    lo = make_uint4(l[0], l[1], l[2], l[3]);
}

// ---------------- 1) fold LoRA into dense weights + fp16 split ----------------
__global__ __launch_bounds__(256)
void fold_split_kernel(const float* __restrict__ w,
                       const float* __restrict__ l1,
                       const float* __restrict__ l2,
                       int oi)
{
    int row = blockIdx.x;
    int c0  = threadIdx.x * 8;
    float acc[8];
    const float4* wp = (const float4*)(w + (size_t)row*DIM + c0);
    float4 a = wp[0], b = wp[1];
    acc[0]=a.x; acc[1]=a.y; acc[2]=a.z; acc[3]=a.w;
    acc[4]=b.x; acc[5]=b.y; acc[6]=b.z; acc[7]=b.w;
#pragma unroll
    for (int r = 0; r < RR; r++){
        float s = __ldg(&l2[row*RR + r]);
        const float4* lp = (const float4*)(l1 + (size_t)r*DIM + c0);
        float4 u = lp[0], v = lp[1];
        acc[0]+=s*u.x; acc[1]+=s*u.y; acc[2]+=s*u.z; acc[3]+=s*u.w;
        acc[4]+=s*v.x; acc[5]+=s*v.y; acc[6]+=s*v.z; acc[7]+=s*v.w;
    }
    uint4 hi, lo; split8h(acc, hi, lo);
    *(uint4*)(&g_whi[oi][(size_t)row*DIM + c0]) = hi;
    *(uint4*)(&g_wlo[oi][(size_t)row*DIM + c0]) = lo;
}

// ---------------- 2) split activations into fp16 hi/lo ----------------
__global__ __launch_bounds__(256)
void split_x_kernel(const float* __restrict__ src, int use_comb)
{
    size_t i = (size_t)(blockIdx.x*256 + threadIdx.x) * 8;
    const float* s = use_comb ? g_comb : src;
    const float4* p = (const float4*)(s + i);
    float4 a = p[0], b = p[1];
    float v[8] = {a.x,a.y,a.z,a.w,b.x,b.y,b.z,b.w};
    uint4 hi, lo; split8h(v, hi, lo);
    *(uint4*)(&g_xhi[i]) = hi;
    *(uint4*)(&g_xlo[i]) = lo;
}

// ---------------- 3) HMMA fp16-split GEMM: Y(M,N) = X(M,K) @ W(N,K)^T ----------
// 128x128 CTA tile, 8 warps (2x4), 64x32 warp tiles, K-chunk 32, cp.async double buffer.
#define KC 32
#define PITCH 40            // halves per smem row (80B, conflict-free ldmatrix)
#define MAT_BYTES (128*PITCH*2)   // 10240
#define OFF_AH 0
#define OFF_AL (1*MAT_BYTES)
#define OFF_BH (2*MAT_BYTES)
#define OFF_BL (3*MAT_BYTES)
#define STAGE  (4*MAT_BYTES)      // 40960
#define NCH (DIM/KC)              // 64

#define CP16(dst, src) asm volatile("cp.async.cg.shared.global [%0], [%1], 16;" :: "r"(dst), "l"(src))
#define CPCOMMIT()  asm volatile("cp.async.commit_group;" ::: "memory")
#define CPWAIT1()   asm volatile("cp.async.wait_group 1;" ::: "memory")
#define CPWAIT0()   asm volatile("cp.async.wait_group 0;" ::: "memory")
#define LDM4(r0,r1,r2,r3,addr) \
    asm volatile("ldmatrix.sync.aligned.m8n8.x4.shared.b16 {%0,%1,%2,%3}, [%4];" \
        : "=r"(r0), "=r"(r1), "=r"(r2), "=r"(r3) : "r"(addr))
#define MMA16816(c, a0,a1,a2,a3, b0,b1) \
    asm volatile("mma.sync.aligned.m16n8k16.row.col.f32.f16.f16.f32 " \
        "{%0,%1,%2,%3}, {%4,%5,%6,%7}, {%8,%9}, {%0,%1,%2,%3};" \
        : "+f"((c)[0]), "+f"((c)[1]), "+f"((c)[2]), "+f"((c)[3]) \
        : "r"(a0), "r"(a1), "r"(a2), "r"(a3), "r"(b0), "r"(b1))

__global__ __launch_bounds__(256)
void gemm_mma(int widx, float* __restrict__ Yext, int ysel)
{
    extern __shared__ char dsm[];
    float* Y = (ysel==0) ? g_xq : (ysel==1) ? g_xk : (ysel==2) ? g_xv : Yext;
    const __half* Bhp = g_whi[widx];
    const __half* Blp = g_wlo[widx];

    int t = threadIdx.x, lane = t & 31, wid = t >> 5;
    int wm = wid >> 2, wn = wid & 3;
    int m0 = blockIdx.y * 128, n0 = blockIdx.x * 128;

    uint32_t sb0 = smem_u32(dsm);

    // prefetch mapping: thread -> row (0..127), 16-half column segment (0 or 16)
    int pr = t >> 1, pc = (t & 1) * 16;
    const __half* gAh = g_xhi + (size_t)(m0 + pr)*DIM + pc;
    const __half* gAl = g_xlo + (size_t)(m0 + pr)*DIM + pc;
    const __half* gBh = Bhp   + (size_t)(n0 + pr)*DIM + pc;
    const __half* gBl = Blp   + (size_t)(n0 + pr)*DIM + pc;
    uint32_t dA = sb0 + (uint32_t)((pr*PITCH + pc)*2);

    float acc[4][4][4];
#pragma unroll
    for (int i = 0; i < 4; i++)
#pragma unroll
        for (int j = 0; j < 4; j++)
#pragma unroll
            for (int k = 0; k < 4; k++) acc[i][j][k] = 0.f;

    // prefetch chunk 0
    {
        uint32_t d = dA;
        CP16(d + OFF_AH,      gAh);     CP16(d + OFF_AH + 16, gAh + 8);
        CP16(d + OFF_AL,      gAl);     CP16(d + OFF_AL + 16, gAl + 8);
        CP16(d + OFF_BH,      gBh);     CP16(d + OFF_BH + 16, gBh + 8);
        CP16(d + OFF_BL,      gBl);     CP16(d + OFF_BL + 16, gBl + 8);
        CPCOMMIT();
    }

#pragma unroll 1
    for (int ch = 0; ch < NCH; ch++){
        if (ch + 1 < NCH){
            int k0 = (ch + 1) * KC;
            uint32_t d = dA + ((ch + 1) & 1) * STAGE;
            CP16(d + OFF_AH,      gAh + k0);     CP16(d + OFF_AH + 16, gAh + k0 + 8);
            CP16(d + OFF_AL,      gAl + k0);     CP16(d + OFF_AL + 16, gAl + k0 + 8);
            CP16(d + OFF_BH,      gBh + k0);     CP16(d + OFF_BH + 16, gBh + k0 + 8);
            CP16(d + OFF_BL,      gBl + k0);     CP16(d + OFF_BL + 16, gBl + k0 + 8);
            CPCOMMIT();
            CPWAIT1();
        } else {
            CPWAIT0();
        }
        __syncthreads();

        uint32_t base = sb0 + (ch & 1) * STAGE;
        int rsel = (lane & 15);
        int csel = (lane >> 4) * 8;
#pragma unroll
        for (int ks = 0; ks < 2; ks++){
            int kofs = ks*16 + csel;
            uint32_t Bh[8], Bl[8];
#pragma unroll
            for (int p = 0; p < 2; p++){
                uint32_t ab = base + OFF_BH + (uint32_t)(((wn*32 + p*16 + rsel)*PITCH + kofs)*2);
                uint32_t r0,r1,r2,r3;
                LDM4(r0,r1,r2,r3, ab);
                Bh[4*p+0]=r0; Bh[4*p+1]=r2; Bh[4*p+2]=r1; Bh[4*p+3]=r3;
                uint32_t lb = ab + (OFF_BL - OFF_BH);
                LDM4(r0,r1,r2,r3, lb);
                Bl[4*p+0]=r0; Bl[4*p+1]=r2; Bl[4*p+2]=r1; Bl[4*p+3]=r3;
            }
#pragma unroll
            for (int mt = 0; mt < 4; mt++){
                uint32_t aa = base + OFF_AH + (uint32_t)(((wm*64 + mt*16 + rsel)*PITCH + kofs)*2);
                uint32_t ah0,ah1,ah2,ah3, al0,al1,al2,al3;
                LDM4(ah0,ah1,ah2,ah3, aa);
                LDM4(al0,al1,al2,al3, aa + (OFF_AL - OFF_AH));
#pragma unroll
                for (int nt = 0; nt < 4; nt++){
                    int p = nt >> 1, o = nt & 1;
                    uint32_t b0h = Bh[4*p + 2*o], b1h = Bh[4*p + 2*o + 1];
                    uint32_t b0l = Bl[4*p + 2*o], b1l = Bl[4*p + 2*o + 1];
                    MMA16816(acc[mt][nt], ah0,ah1,ah2,ah3, b0h,b1h);
                    MMA16816(acc[mt][nt], ah0,ah1,ah2,ah3, b0l,b1l);
                    MMA16816(acc[mt][nt], al0,al1,al2,al3, b0h,b1h);
                }
            }
        }
        __syncthreads();
    }

    // epilogue
    int grp = lane >> 2, tig = lane & 3;
#pragma unroll
    for (int mt = 0; mt < 4; mt++){
#pragma unroll
        for (int nt = 0; nt < 4; nt++){
            int r0 = m0 + wm*64 + mt*16 + grp;
            int c  = n0 + wn*32 + nt*8 + tig*2;
            *(float2*)&Y[(size_t)r0*DIM + c]       = make_float2(acc[mt][nt][0], acc[mt][nt][1]);
            *(float2*)&Y[(size_t)(r0+8)*DIM + c]   = make_float2(acc[mt][nt][2], acc[mt][nt][3]);
        }
    }
}

// ---------------- 4) memory-branch statistics per (b,h) ----------------
__global__ __launch_bounds__(256)
void mem_stats_kernel(const float* __restrict__ cache_k,
                      const float* __restrict__ cache_v,
                      const float* __restrict__ pquery,
                      const float* __restrict__ meml_in,
                      const float* __restrict__ memq_in,
                      const float* __restrict__ nrm_in)
{
    int bh = blockIdx.x;
    int b = bh >> 5, h = bh & 31;
    __shared__ float Ks[32][64];
    __shared__ float Vs[32][64];
    __shared__ float pqs[64];
    __shared__ float sig[32];

    int t = threadIdx.x;
    if (t < 64) pqs[t] = pquery[(b*HH + h)*HD + t];

    float accl[4][4] = {{0}}, accq[4][4] = {{0}};
    float accn = 0.f;
    int lrow = t >> 3;
    int lcol = (t & 7) * 8;
    int d0 = (t >> 4) * 4;
    int e0 = (t & 15) * 4;

    for (int s0 = 0; s0 < SS; s0 += 32) {
        __syncthreads();
        const float* kp = cache_k + ((size_t)((b*SS + s0 + lrow)*HH + h))*HD + lcol;
        const float* vp = cache_v + ((size_t)((b*SS + s0 + lrow)*HH + h))*HD + lcol;
        *(float4*)&Ks[lrow][lcol]   = *(const float4*)kp;
        *(float4*)&Ks[lrow][lcol+4] = *(const float4*)(kp + 4);
        *(float4*)&Vs[lrow][lcol]   = *(const float4*)vp;
        *(float4*)&Vs[lrow][lcol+4] = *(const float4*)(vp + 4);
        __syncthreads();
        if (t < 32) {
            float sum = 0.f;
#pragma unroll
            for (int d = 0; d < 64; d++) sum += pqs[d] * Ks[t][d];
            sig[t] = sigmf(sum * 0.125f);
        }
        __syncthreads();
#pragma unroll
        for (int u = 0; u < 8; u++) Ks[lrow][lcol+u] = elu1f(Ks[lrow][lcol+u]);
        __syncthreads();
        if (t < 64) {
#pragma unroll
            for (int s = 0; s < 32; s++) accn += Ks[s][t];
        }
#pragma unroll 4
        for (int s = 0; s < 32; s++) {
            float4 k4 = *(const float4*)&Ks[s][d0];
            float4 v4 = *(const float4*)&Vs[s][e0];
            float sg = sig[s];
            float ka[4] = {k4.x, k4.y, k4.z, k4.w};
            float kb[4] = {k4.x*sg, k4.y*sg, k4.z*sg, k4.w*sg};
            float vv[4] = {v4.x, v4.y, v4.z, v4.w};
#pragma unroll
            for (int i = 0; i < 4; i++)
#pragma unroll
                for (int j = 0; j < 4; j++) {
                    accl[i][j] += ka[i] * vv[j];
                    accq[i][j] += kb[i] * vv[j];
                }
        }
    }
    size_t base = (size_t)bh * HD * HD;
#pragma unroll
    for (int i = 0; i < 4; i++)
#pragma unroll
        for (int j = 0; j < 4; j++) {
            size_t idx = base + (size_t)(d0 + i)*HD + (e0 + j);
            g_meml[idx] = meml_in[idx] + accl[i][j];
            g_memq[idx] = memq_in[idx] + accq[i][j];
        }
    if (t < 64) g_nrmt[bh*HD + t] = nrm_in[bh*HD + t] + accn;
}

// ---------------- 5) memory-branch apply: g * mem_comb -> g_comb ----------------
__global__ __launch_bounds__(256)
void mem_apply_kernel(const float* __restrict__ gmem_w,
                      const float* __restrict__ gmem_b,
                      const float* __restrict__ gate)
{
    int idx = blockIdx.x;
    int st = idx & 31;
    int h  = (idx >> 5) & 31;
    int b  = idx >> 10;
    int bh = b*HH + h;
    int s0 = st * 32;

    __shared__ float ml[64*64];
    __shared__ float mq[64*64];
    __shared__ float sq[32*68];
    __shared__ float nrm[64];
    __shared__ float wv[64];
    __shared__ float gpart[32*8];

    int t = threadIdx.x;
    {
        int r = t >> 2, c = (t & 3) * 16;
        size_t gbase = (size_t)bh*HD*HD + (size_t)r*HD + c;
#pragma unroll
        for (int u = 0; u < 4; u++) {
            *(float4*)&ml[r*64 + c + 4*u] = *(const float4*)&g_meml[gbase + 4*u];
            *(float4*)&mq[r*64 + c + 4*u] = *(const float4*)&g_memq[gbase + 4*u];
        }
    }
    {
        int r = t >> 3, c = (t & 7) * 8;
        const float* xp = g_xq + ((size_t)((b*SS + s0 + r)*HH + h))*HD + c;
        float4 a = *(const float4*)xp;
        float4 bv = *(const float4*)(xp + 4);
        float4 ea = make_float4(elu1f(a.x), elu1f(a.y), elu1f(a.z), elu1f(a.w));
        float4 eb = make_float4(elu1f(bv.x), elu1f(bv.y), elu1f(bv.z), elu1f(bv.w));
        *(float4*)&sq[r*68 + c]     = ea;
        *(float4*)&sq[r*68 + c + 4] = eb;
    }
    if (t < 64) { nrm[t] = g_nrmt[bh*HD + t]; wv[t] = gmem_w[t]; }
    __syncthreads();

    int row = t >> 3;
    int eq  = t & 7;
    float denom = 0.f;
#pragma unroll
    for (int d = 0; d < 64; d++) denom += sq[row*68 + d] * nrm[d];

    float4 mo[2]  = {make_float4(0,0,0,0), make_float4(0,0,0,0)};
    float4 qmo[2] = {make_float4(0,0,0,0), make_float4(0,0,0,0)};
#pragma unroll
    for (int d = 0; d < 64; d++) {
        float sd = sq[row*68 + d];
#pragma unroll
        for (int c = 0; c < 2; c++) {
            float4 m4 = *(const float4*)&ml[d*64 + eq*4 + 32*c];
            float4 q4 = *(const float4*)&mq[d*64 + eq*4 + 32*c];
            mo[c].x += sd*m4.x; mo[c].y += sd*m4.y; mo[c].z += sd*m4.z; mo[c].w += sd*m4.w;
            qmo[c].x += sd*q4.x; qmo[c].y += sd*q4.y; qmo[c].z += sd*q4.z; qmo[c].w += sd*q4.w;
        }
    }
    float inv = 1.f / denom;
    float gp = 0.f;
#pragma unroll
    for (int c = 0; c < 2; c++) {
        mo[c].x *= inv; mo[c].y *= inv; mo[c].z *= inv; mo[c].w *= inv;
        qmo[c].x *= inv; qmo[c].y *= inv; qmo[c].z *= inv; qmo[c].w *= inv;
        int e = eq*4 + 32*c;
        gp += qmo[c].x*wv[e] + qmo[c].y*wv[e+1] + qmo[c].z*wv[e+2] + qmo[c].w*wv[e+3];
    }
    gpart[row*8 + eq] = gp;
    __syncthreads();
    float gsum = 0.f;
#pragma unroll
    for (int i = 0; i < 8; i++) gsum += gpart[row*8 + i];
    float gq = sigmf(gsum + gmem_b[0]);
    float gh = sigmf(gate[h]);

    float* op = g_comb + ((size_t)((b*SS + s0 + row)*HH + h))*HD;
#pragma unroll
    for (int c = 0; c < 2; c++) {
        float4 o;
        o.x = gh * (mo[c].x + gq*qmo[c].x);
        o.y = gh * (mo[c].y + gq*qmo[c].y);
        o.z = gh * (mo[c].z + gq*qmo[c].z);
        o.w = gh * (mo[c].w + gq*qmo[c].w);
        *(float4*)(op + eq*4 + 32*c) = o;
    }
}

// ---------------- 6) RoPE for q and k ----------------
__global__ void rope_kernel(const float* __restrict__ fc, const float* __restrict__ fs)
{
    int idx = blockIdx.x * 256 + threadIdx.x;
    int i = idx & 31;
    int s = (idx >> 10) & 1023;
    size_t pos = (size_t)idx * 2;
    float c = fc[s*32 + i];
    float sn = fs[s*32 + i];
    float a = g_xq[pos], b2 = g_xq[pos+1];
    g_qr[pos]   = a*c - b2*sn;
    g_qr[pos+1] = a*sn + b2*c;
    a = g_xk[pos]; b2 = g_xk[pos+1];
    g_kr[pos]   = a*c - b2*sn;
    g_kr[pos+1] = a*sn + b2*c;
}

// ---------------- 7) causal flash attention + combine ----------------
__global__ __launch_bounds__(256, 1)
void flash_kernel(const float* __restrict__ gate)
{
    extern __shared__ float sm[];
    float* Ks   = sm;
    float* Vs   = Ks + 64*68;
    float* Ps   = Vs + 64*68;
    float* rmax = Ps + 64*68;
    float* rsum = rmax + 256;

    int t  = threadIdx.x;
    int qt = blockIdx.x & 15;
    int h  = (blockIdx.x >> 4) & 31;
    int b  = blockIdx.x >> 9;
    int row = t >> 2;
    int eq  = t & 3;
    int qglob = qt*64 + row;

    float4 qv[16];
    const float* qp = g_qr + ((size_t)((b*SS + qglob)*HH + h))*HD;
#pragma unroll
    for (int u = 0; u < 16; u++) {
        float4 v = *(const float4*)(qp + 4*u);
        v.x *= 0.125f; v.y *= 0.125f; v.z *= 0.125f; v.w *= 0.125f;
        qv[u] = v;
    }

    float m = -INFINITY, l = 0.f;
    float4 O[4] = {make_float4(0,0,0,0), make_float4(0,0,0,0),
                   make_float4(0,0,0,0), make_float4(0,0,0,0)};

    for (int kt = 0; kt <= qt; kt++) {
        __syncthreads();
        {
            const float* kp = g_kr + ((size_t)((b*SS + kt*64 + row)*HH + h))*HD + eq*16;
            const float* vp = g_xv + ((size_t)((b*SS + kt*64 + row)*HH + h))*HD + eq*16;
#pragma unroll
            for (int u = 0; u < 4; u++) {
                *(float4*)&Ks[row*68 + eq*16 + 4*u] = *(const float4*)(kp + 4*u);
                *(float4*)&Vs[row*68 + eq*16 + 4*u] = *(const float4*)(vp + 4*u);
            }
        }
        __syncthreads();

        float lmax = -INFINITY;
#pragma unroll
        for (int j = 0; j < 16; j++) {
            int kc = eq*16 + j;
            float sv = 0.f;
#pragma unroll
            for (int u = 0; u < 16; u++) {
                float4 k4 = *(const float4*)&Ks[kc*68 + 4*u];
                sv += qv[u].x*k4.x + qv[u].y*k4.y + qv[u].z*k4.z + qv[u].w*k4.w;
            }
            if (kt == qt && kc > row) sv = -INFINITY;
            Ps[row*68 + kc] = sv;
            lmax = fmaxf(lmax, sv);
        }
        rmax[row*4 + eq] = lmax;
        __syncthreads();
        float tmax = fmaxf(fmaxf(rmax[row*4+0], rmax[row*4+1]),
                           fmaxf(rmax[row*4+2], rmax[row*4+3]));
        float mnew = fmaxf(m, tmax);
        float corr = __expf(m - mnew);
        float lsum = 0.f;
#pragma unroll
        for (int j = 0; j < 16; j++) {
            int kc = eq*16 + j;
            float p = __expf(Ps[row*68 + kc] - mnew);
            Ps[row*68 + kc] = p;
            lsum += p;
        }
        rsum[row*4 + eq] = lsum;
        __syncthreads();
        float tsum = rsum[row*4+0] + rsum[row*4+1] + rsum[row*4+2] + rsum[row*4+3];
        l = l * corr + tsum;
        m = mnew;
#pragma unroll
        for (int c = 0; c < 4; c++) {
            O[c].x *= corr; O[c].y *= corr; O[c].z *= corr; O[c].w *= corr;
        }
#pragma unroll 8
        for (int kc = 0; kc < 64; kc++) {
            float p = Ps[row*68 + kc];
#pragma unroll
            for (int c = 0; c < 4; c++) {
                float4 v4 = *(const float4*)&Vs[kc*68 + eq*4 + 16*c];
                O[c].x += p*v4.x; O[c].y += p*v4.y; O[c].z += p*v4.z; O[c].w += p*v4.w;
            }
        }
    }

    float gh = sigmf(gate[h]);
    float w1 = (1.f - gh) / l;
    float* op = g_comb + ((size_t)((b*SS + qglob)*HH + h))*HD;
#pragma unroll
    for (int c = 0; c < 4; c++) {
        int e = eq*4 + 16*c;
        float4 prev = *(const float4*)(op + e);
        float4 o;
        o.x = prev.x + w1*O[c].x;
        o.y = prev.y + w1*O[c].y;
        o.z = prev.z + w1*O[c].z;
        o.w = prev.w + w1*O[c].w;
        *(float4*)(op + e) = o;
    }
}

// ---------------- launcher ----------------
extern "C" void kernel_launch(void* const* d_in, const int* in_sizes, int n_in,
                              void* d_out, int out_size)
{
    const float* x     = (const float*)d_in[0];
    const float* pq    = (const float*)d_in[1];
    const float* ck    = (const float*)d_in[2];
    const float* cv    = (const float*)d_in[3];
    const float* meml  = (const float*)d_in[4];
    const float* memq  = (const float*)d_in[5];
    const float* nrm   = (const float*)d_in[6];
    const float* fc    = (const float*)d_in[7];
    const float* fs    = (const float*)d_in[8];
    const float* wq    = (const float*)d_in[10];
    const float* wk    = (const float*)d_in[11];
    const float* wv    = (const float*)d_in[12];
    const float* wo    = (const float*)d_in[13];
    const float* lq1   = (const float*)d_in[14];
    const float* lq2   = (const float*)d_in[15];
    const float* lk1   = (const float*)d_in[16];
    const float* lk2   = (const float*)d_in[17];
    const float* lv1   = (const float*)d_in[18];
    const float* lv2   = (const float*)d_in[19];
    const float* lo1   = (const float*)d_in[20];
    const float* lo2   = (const float*)d_in[21];
    const float* gate  = (const float*)d_in[22];
    const float* gw    = (const float*)d_in[23];
    const float* gb    = (const float*)d_in[24];
    float* out = (float*)d_out;

    fold_split_kernel<<<DIM, 256>>>(wq, lq1, lq2, 0);
    fold_split_kernel<<<DIM, 256>>>(wk, lk1, lk2, 1);
    fold_split_kernel<<<DIM, 256>>>(wv, lv1, lv2, 2);
    fold_split_kernel<<<DIM, 256>>>(wo, lo1, lo2, 3);

    split_x_kernel<<<(MM*DIM)/(256*8), 256>>>(x, 0);

    size_t gsm = 2 * STAGE;          // 81920 B
    cudaFuncSetAttribute(gemm_mma, cudaFuncAttributeMaxDynamicSharedMemorySize, (int)gsm);
    dim3 gg(DIM/128, MM/128);
    gemm_mma<<<gg, 256, gsm>>>(0, nullptr, 0);   // xq
    gemm_mma<<<gg, 256, gsm>>>(1, nullptr, 1);   // xk
    gemm_mma<<<gg, 256, gsm>>>(2, nullptr, 2);   // xv

    mem_stats_kernel<<<BB*HH, 256>>>(ck, cv, pq, meml, memq, nrm);
    mem_apply_kernel<<<BB*HH*(SS/32), 256>>>(gw, gb, gate);

    rope_kernel<<<(BB*SS*HH*32)/256, 256>>>(fc, fs);

    size_t fl_smem = (size_t)(3*64*68 + 512) * sizeof(float);
    cudaFuncSetAttribute(flash_kernel, cudaFuncAttributeMaxDynamicSharedMemorySize,
                         (int)fl_smem);
    flash_kernel<<<BB*HH*(SS/64), 256, fl_smem>>>(gate);

    split_x_kernel<<<(MM*DIM)/(256*8), 256>>>(nullptr, 1);
    gemm_mma<<<gg, 256, gsm>>>(3, out, 3);       // final projection
    (void)in_sizes; (void)n_in; (void)out_size;
}

// round 4
// speedup vs baseline: 1.6733x; 1.1267x over previous
#include <cuda_runtime.h>
#include <cuda_fp16.h>
#include <math.h>
#include <stdint.h>

// Problem constants
#define BB 4
#define SS 1024
#define DIM 2048
#define HH 32
#define HD 64
#define RR 16
#define MM (BB*SS)   // 4096

// ---------------- scratch (device globals; no allocation allowed) ----------------
__device__ __half g_whi[4][DIM*DIM];
__device__ __half g_wlo[4][DIM*DIM];
__device__ __half g_xhi[MM*DIM];
__device__ float g_xq[MM*DIM];
__device__ float g_xk[MM*DIM];
__device__ float g_xv[MM*DIM];
__device__ float g_qr[MM*DIM];
__device__ float g_kr[MM*DIM];
__device__ float g_meml[BB*HH*HD*HD];
__device__ float g_memq[BB*HH*HD*HD];
__device__ float g_nrmt[BB*HH*HD];
__device__ float g_comb[MM*DIM];

__device__ __forceinline__ float elu1f(float x){ return x > 0.f ? x + 1.f : __expf(x); }
__device__ __forceinline__ float sigmf(float x){ return 1.f/(1.f+__expf(-x)); }

__device__ __forceinline__ uint32_t smem_u32(const void* p){
    uint32_t a;
    asm("{ .reg .u64 t; cvta.to.shared.u64 t, %1; cvt.u32.u64 %0, t; }" : "=r"(a) : "l"(p));
    return a;
}

// ---------------- fp16 hi/lo split of 8 floats -> 2 uint4 ----------------
__device__ __forceinline__ void split8h(const float* v, uint4& hi, uint4& lo){
    unsigned h[4], l[4];
#pragma unroll
    for (int p = 0; p < 4; p++){
        __half h0 = __float2half_rn(v[2*p]);
        __half h1 = __float2half_rn(v[2*p+1]);
        __half l0 = __float2half_rn(v[2*p]   - __half2float(h0));
        __half l1 = __float2half_rn(v[2*p+1] - __half2float(h1));
        h[p] = (unsigned)__half_as_ushort(h0) | ((unsigned)__half_as_ushort(h1) << 16);
        l[p] = (unsigned)__half_as_ushort(l0) | ((unsigned)__half_as_ushort(l1) << 16);
    }
    hi = make_uint4(h[0], h[1], h[2], h[3]);
    lo = make_uint4(l[0], l[1], l[2], l[3]);
}

// ---------------- 1) fold LoRA into dense weights + fp16 split ----------------
__global__ __launch_bounds__(256)
void fold_split_kernel(const float* __restrict__ w,
                       const float* __restrict__ l1,
                       const float* __restrict__ l2,
                       int oi)
{
    int row = blockIdx.x;
    int c0  = threadIdx.x * 8;
    float acc[8];
    const float4* wp = (const float4*)(w + (size_t)row*DIM + c0);
    float4 a = wp[0], b = wp[1];
    acc[0]=a.x; acc[1]=a.y; acc[2]=a.z; acc[3]=a.w;
    acc[4]=b.x; acc[5]=b.y; acc[6]=b.z; acc[7]=b.w;
#pragma unroll
    for (int r = 0; r < RR; r++){
        float s = __ldg(&l2[row*RR + r]);
        const float4* lp = (const float4*)(l1 + (size_t)r*DIM + c0);
        float4 u = lp[0], v = lp[1];
        acc[0]+=s*u.x; acc[1]+=s*u.y; acc[2]+=s*u.z; acc[3]+=s*u.w;
        acc[4]+=s*v.x; acc[5]+=s*v.y; acc[6]+=s*v.z; acc[7]+=s*v.w;
    }
    uint4 hi, lo; split8h(acc, hi, lo);
    *(uint4*)(&g_whi[oi][(size_t)row*DIM + c0]) = hi;
    *(uint4*)(&g_wlo[oi][(size_t)row*DIM + c0]) = lo;
}

// ---------------- 2) convert activations to fp16 (hi only) ----------------
__global__ __launch_bounds__(256)
void split_x_kernel(const float* __restrict__ src, int use_comb)
{
    size_t i = (size_t)(blockIdx.x*256 + threadIdx.x) * 8;
    const float* s = use_comb ? g_comb : src;
    const float4* p = (const float4*)(s + i);
    float4 a = p[0], b = p[1];
    unsigned h[4];
    h[0] = (unsigned)__half_as_ushort(__float2half_rn(a.x)) | ((unsigned)__half_as_ushort(__float2half_rn(a.y)) << 16);
    h[1] = (unsigned)__half_as_ushort(__float2half_rn(a.z)) | ((unsigned)__half_as_ushort(__float2half_rn(a.w)) << 16);
    h[2] = (unsigned)__half_as_ushort(__float2half_rn(b.x)) | ((unsigned)__half_as_ushort(__float2half_rn(b.y)) << 16);
    h[3] = (unsigned)__half_as_ushort(__float2half_rn(b.z)) | ((unsigned)__half_as_ushort(__float2half_rn(b.w)) << 16);
    *(uint4*)(&g_xhi[i]) = make_uint4(h[0], h[1], h[2], h[3]);
}

// ---------------- 3) HMMA 2-term GEMM: Y(M,N) = X(M,K) @ W(N,K)^T --------------
// 128x128 CTA tile, 8 warps (2x4), K-chunk 32, 3-stage cp.async ring, 1 sync/chunk.
// Terms: Ah*Bh + Ah*Bl (fp32 accum). Dropped Al*Bh ~ 2.8e-4 RMS rel.
#define KC 32
#define PITCH 40                      // halves per smem row (80B, conflict-free)
#define SMAT (128*PITCH*2)            // 10240 B per matrix
#define OFF_AH 0
#define OFF_BH SMAT
#define OFF_BL (2*SMAT)
#define STG_BYTES (3*SMAT)            // 30720
#define NSTG 3
#define NCH (DIM/KC)                  // 64

#define CP16(dst, src) asm volatile("cp.async.cg.shared.global [%0], [%1], 16;" :: "r"(dst), "l"(src))
#define CPCOMMIT()  asm volatile("cp.async.commit_group;" ::: "memory")
#define CPWAIT1()   asm volatile("cp.async.wait_group 1;" ::: "memory")
#define CPWAIT0()   asm volatile("cp.async.wait_group 0;" ::: "memory")
#define LDM4(r0,r1,r2,r3,addr) \
    asm volatile("ldmatrix.sync.aligned.m8n8.x4.shared.b16 {%0,%1,%2,%3}, [%4];" \
        : "=r"(r0), "=r"(r1), "=r"(r2), "=r"(r3) : "r"(addr))
#define MMA16816(c, a0,a1,a2,a3, b0,b1) \
    asm volatile("mma.sync.aligned.m16n8k16.row.col.f32.f16.f16.f32 " \
        "{%0,%1,%2,%3}, {%4,%5,%6,%7}, {%8,%9}, {%0,%1,%2,%3};" \
        : "+f"((c)[0]), "+f"((c)[1]), "+f"((c)[2]), "+f"((c)[3]) \
        : "r"(a0), "r"(a1), "r"(a2), "r"(a3), "r"(b0), "r"(b1))

__global__ __launch_bounds__(256, 2)
void gemm_mma(int widx, float* __restrict__ Yext, int ysel)
{
    extern __shared__ char dsm[];
    float* Y = (ysel==0) ? g_xq : (ysel==1) ? g_xk : (ysel==2) ? g_xv : Yext;
    const __half* Bhp = g_whi[widx];
    const __half* Blp = g_wlo[widx];

    int t = threadIdx.x, lane = t & 31, wid = t >> 5;
    int wm = wid >> 2, wn = wid & 3;
    int m0 = blockIdx.y * 128, n0 = blockIdx.x * 128;

    uint32_t sb0 = smem_u32(dsm);

    // prefetch mapping: thread -> row (0..127), 16-half column segment (0 or 16)
    int pr = t >> 1, pc = (t & 1) * 16;
    const __half* gAh = g_xhi + (size_t)(m0 + pr)*DIM + pc;
    const __half* gBh = Bhp   + (size_t)(n0 + pr)*DIM + pc;
    const __half* gBl = Blp   + (size_t)(n0 + pr)*DIM + pc;
    uint32_t dA = sb0 + (uint32_t)((pr*PITCH + pc)*2);

    float acc[4][4][4];
#pragma unroll
    for (int i = 0; i < 4; i++)
#pragma unroll
        for (int j = 0; j < 4; j++)
#pragma unroll
            for (int k = 0; k < 4; k++) acc[i][j][k] = 0.f;

    // prologue: prefetch chunks 0,1
#pragma unroll
    for (int c = 0; c < 2; c++){
        uint32_t d = dA + c*STG_BYTES;
        int k0 = c*KC;
        CP16(d + OFF_AH, gAh + k0);  CP16(d + OFF_AH + 16, gAh + k0 + 8);
        CP16(d + OFF_BH, gBh + k0);  CP16(d + OFF_BH + 16, gBh + k0 + 8);
        CP16(d + OFF_BL, gBl + k0);  CP16(d + OFF_BL + 16, gBl + k0 + 8);
        CPCOMMIT();
    }

    int rsel = (lane & 15);
    int csel = (lane >> 4) * 8;
    int stg = 0, pstg = 2;

#pragma unroll 1
    for (int ch = 0; ch < NCH; ch++){
        if (ch == NCH - 1) { CPWAIT0(); } else { CPWAIT1(); }
        __syncthreads();

        if (ch + 2 < NCH){
            uint32_t d = dA + pstg*STG_BYTES;
            int k0 = (ch + 2)*KC;
            CP16(d + OFF_AH, gAh + k0);  CP16(d + OFF_AH + 16, gAh + k0 + 8);
            CP16(d + OFF_BH, gBh + k0);  CP16(d + OFF_BH + 16, gBh + k0 + 8);
            CP16(d + OFF_BL, gBl + k0);  CP16(d + OFF_BL + 16, gBl + k0 + 8);
            CPCOMMIT();
            pstg = (pstg == 2) ? 0 : pstg + 1;
        }

        uint32_t base = sb0 + stg*STG_BYTES;
        stg = (stg == 2) ? 0 : stg + 1;
#pragma unroll
        for (int ks = 0; ks < 2; ks++){
            int kofs = ks*16 + csel;
            uint32_t Bh[8], Bl[8];
#pragma unroll
            for (int p = 0; p < 2; p++){
                uint32_t ab = base + OFF_BH + (uint32_t)(((wn*32 + p*16 + rsel)*PITCH + kofs)*2);
                uint32_t r0,r1,r2,r3;
                LDM4(r0,r1,r2,r3, ab);
                Bh[4*p+0]=r0; Bh[4*p+1]=r2; Bh[4*p+2]=r1; Bh[4*p+3]=r3;
                LDM4(r0,r1,r2,r3, ab + (OFF_BL - OFF_BH));
                Bl[4*p+0]=r0; Bl[4*p+1]=r2; Bl[4*p+2]=r1; Bl[4*p+3]=r3;
            }
#pragma unroll
            for (int mt = 0; mt < 4; mt++){
                uint32_t aa = base + OFF_AH + (uint32_t)(((wm*64 + mt*16 + rsel)*PITCH + kofs)*2);
                uint32_t a0,a1,a2,a3;
                LDM4(a0,a1,a2,a3, aa);
#pragma unroll
                for (int nt = 0; nt < 4; nt++){
                    int p = nt >> 1, o = nt & 1;
                    MMA16816(acc[mt][nt], a0,a1,a2,a3, Bh[4*p + 2*o], Bh[4*p + 2*o + 1]);
                    MMA16816(acc[mt][nt], a0,a1,a2,a3, Bl[4*p + 2*o], Bl[4*p + 2*o + 1]);
                }
            }
        }
    }

    // epilogue
    int grp = lane >> 2, tig = lane & 3;
#pragma unroll
    for (int mt = 0; mt < 4; mt++){
#pragma unroll
        for (int nt = 0; nt < 4; nt++){
            int r0 = m0 + wm*64 + mt*16 + grp;
            int c  = n0 + wn*32 + nt*8 + tig*2;
            *(float2*)&Y[(size_t)r0*DIM + c]       = make_float2(acc[mt][nt][0], acc[mt][nt][1]);
            *(float2*)&Y[(size_t)(r0+8)*DIM + c]   = make_float2(acc[mt][nt][2], acc[mt][nt][3]);
        }
    }
}

// ---------------- 4) memory-branch statistics per (b,h) ----------------
__global__ __launch_bounds__(256)
void mem_stats_kernel(const float* __restrict__ cache_k,
                      const float* __restrict__ cache_v,
                      const float* __restrict__ pquery,
                      const float* __restrict__ meml_in,
                      const float* __restrict__ memq_in,
                      const float* __restrict__ nrm_in)
{
    int bh = blockIdx.x;
    int b = bh >> 5, h = bh & 31;
    __shared__ float Ks[32][64];
    __shared__ float Vs[32][64];
    __shared__ float pqs[64];
    __shared__ float sig[32];

    int t = threadIdx.x;
    if (t < 64) pqs[t] = pquery[(b*HH + h)*HD + t];

    float accl[4][4] = {{0}}, accq[4][4] = {{0}};
    float accn = 0.f;
    int lrow = t >> 3;
    int lcol = (t & 7) * 8;
    int d0 = (t >> 4) * 4;
    int e0 = (t & 15) * 4;

    for (int s0 = 0; s0 < SS; s0 += 32) {
        __syncthreads();
        const float* kp = cache_k + ((size_t)((b*SS + s0 + lrow)*HH + h))*HD + lcol;
        const float* vp = cache_v + ((size_t)((b*SS + s0 + lrow)*HH + h))*HD + lcol;
        *(float4*)&Ks[lrow][lcol]   = *(const float4*)kp;
        *(float4*)&Ks[lrow][lcol+4] = *(const float4*)(kp + 4);
        *(float4*)&Vs[lrow][lcol]   = *(const float4*)vp;
        *(float4*)&Vs[lrow][lcol+4] = *(const float4*)(vp + 4);
        __syncthreads();
        if (t < 32) {
            float sum = 0.f;
#pragma unroll
            for (int d = 0; d < 64; d++) sum += pqs[d] * Ks[t][d];
            sig[t] = sigmf(sum * 0.125f);
        }
        __syncthreads();
#pragma unroll
        for (int u = 0; u < 8; u++) Ks[lrow][lcol+u] = elu1f(Ks[lrow][lcol+u]);
        __syncthreads();
        if (t < 64) {
#pragma unroll
            for (int s = 0; s < 32; s++) accn += Ks[s][t];
        }
#pragma unroll 4
        for (int s = 0; s < 32; s++) {
            float4 k4 = *(const float4*)&Ks[s][d0];
            float4 v4 = *(const float4*)&Vs[s][e0];
            float sg = sig[s];
            float ka[4] = {k4.x, k4.y, k4.z, k4.w};
            float kb[4] = {k4.x*sg, k4.y*sg, k4.z*sg, k4.w*sg};
            float vv[4] = {v4.x, v4.y, v4.z, v4.w};
#pragma unroll
            for (int i = 0; i < 4; i++)
#pragma unroll
                for (int j = 0; j < 4; j++) {
                    accl[i][j] += ka[i] * vv[j];
                    accq[i][j] += kb[i] * vv[j];
                }
        }
    }
    size_t base = (size_t)bh * HD * HD;
#pragma unroll
    for (int i = 0; i < 4; i++)
#pragma unroll
        for (int j = 0; j < 4; j++) {
            size_t idx = base + (size_t)(d0 + i)*HD + (e0 + j);
            g_meml[idx] = meml_in[idx] + accl[i][j];
            g_memq[idx] = memq_in[idx] + accq[i][j];
        }
    if (t < 64) g_nrmt[bh*HD + t] = nrm_in[bh*HD + t] + accn;
}

// ---------------- 5) memory-branch apply: g * mem_comb -> g_comb ----------------
__global__ __launch_bounds__(256)
void mem_apply_kernel(const float* __restrict__ gmem_w,
                      const float* __restrict__ gmem_b,
                      const float* __restrict__ gate)
{
    int idx = blockIdx.x;
    int st = idx & 31;
    int h  = (idx >> 5) & 31;
    int b  = idx >> 10;
    int bh = b*HH + h;
    int s0 = st * 32;

    __shared__ float ml[64*64];
    __shared__ float mq[64*64];
    __shared__ float sq[32*68];
    __shared__ float nrm[64];
    __shared__ float wv[64];
    __shared__ float gpart[32*8];

    int t = threadIdx.x;
    {
        int r = t >> 2, c = (t & 3) * 16;
        size_t gbase = (size_t)bh*HD*HD + (size_t)r*HD + c;
#pragma unroll
        for (int u = 0; u < 4; u++) {
            *(float4*)&ml[r*64 + c + 4*u] = *(const float4*)&g_meml[gbase + 4*u];
            *(float4*)&mq[r*64 + c + 4*u] = *(const float4*)&g_memq[gbase + 4*u];
        }
    }
    {
        int r = t >> 3, c = (t & 7) * 8;
        const float* xp = g_xq + ((size_t)((b*SS + s0 + r)*HH + h))*HD + c;
        float4 a = *(const float4*)xp;
        float4 bv = *(const float4*)(xp + 4);
        float4 ea = make_float4(elu1f(a.x), elu1f(a.y), elu1f(a.z), elu1f(a.w));
        float4 eb = make_float4(elu1f(bv.x), elu1f(bv.y), elu1f(bv.z), elu1f(bv.w));
        *(float4*)&sq[r*68 + c]     = ea;
        *(float4*)&sq[r*68 + c + 4] = eb;
    }
    if (t < 64) { nrm[t] = g_nrmt[bh*HD + t]; wv[t] = gmem_w[t]; }
    __syncthreads();

    int row = t >> 3;
    int eq  = t & 7;
    float denom = 0.f;
#pragma unroll
    for (int d = 0; d < 64; d++) denom += sq[row*68 + d] * nrm[d];

    float4 mo[2]  = {make_float4(0,0,0,0), make_float4(0,0,0,0)};
    float4 qmo[2] = {make_float4(0,0,0,0), make_float4(0,0,0,0)};
#pragma unroll
    for (int d = 0; d < 64; d++) {
        float sd = sq[row*68 + d];
#pragma unroll
        for (int c = 0; c < 2; c++) {
            float4 m4 = *(const float4*)&ml[d*64 + eq*4 + 32*c];
            float4 q4 = *(const float4*)&mq[d*64 + eq*4 + 32*c];
            mo[c].x += sd*m4.x; mo[c].y += sd*m4.y; mo[c].z += sd*m4.z; mo[c].w += sd*m4.w;
            qmo[c].x += sd*q4.x; qmo[c].y += sd*q4.y; qmo[c].z += sd*q4.z; qmo[c].w += sd*q4.w;
        }
    }
    float inv = 1.f / denom;
    float gp = 0.f;
#pragma unroll
    for (int c = 0; c < 2; c++) {
        mo[c].x *= inv; mo[c].y *= inv; mo[c].z *= inv; mo[c].w *= inv;
        qmo[c].x *= inv; qmo[c].y *= inv; qmo[c].z *= inv; qmo[c].w *= inv;
        int e = eq*4 + 32*c;
        gp += qmo[c].x*wv[e] + qmo[c].y*wv[e+1] + qmo[c].z*wv[e+2] + qmo[c].w*wv[e+3];
    }
    gpart[row*8 + eq] = gp;
    __syncthreads();
    float gsum = 0.f;
#pragma unroll
    for (int i = 0; i < 8; i++) gsum += gpart[row*8 + i];
    float gq = sigmf(gsum + gmem_b[0]);
    float gh = sigmf(gate[h]);

    float* op = g_comb + ((size_t)((b*SS + s0 + row)*HH + h))*HD;
#pragma unroll
    for (int c = 0; c < 2; c++) {
        float4 o;
        o.x = gh * (mo[c].x + gq*qmo[c].x);
        o.y = gh * (mo[c].y + gq*qmo[c].y);
        o.z = gh * (mo[c].z + gq*qmo[c].z);
        o.w = gh * (mo[c].w + gq*qmo[c].w);
        *(float4*)(op + eq*4 + 32*c) = o;
    }
}

// ---------------- 6) RoPE for q and k ----------------
__global__ void rope_kernel(const float* __restrict__ fc, const float* __restrict__ fs)
{
    int idx = blockIdx.x * 256 + threadIdx.x;
    int i = idx & 31;
    int s = (idx >> 10) & 1023;
    size_t pos = (size_t)idx * 2;
    float c = fc[s*32 + i];
    float sn = fs[s*32 + i];
    float a = g_xq[pos], b2 = g_xq[pos+1];
    g_qr[pos]   = a*c - b2*sn;
    g_qr[pos+1] = a*sn + b2*c;
    a = g_xk[pos]; b2 = g_xk[pos+1];
    g_kr[pos]   = a*c - b2*sn;
    g_kr[pos+1] = a*sn + b2*c;
}

// ---------------- 7) causal flash attention + combine ----------------
__global__ __launch_bounds__(256, 1)
void flash_kernel(const float* __restrict__ gate)
{
    extern __shared__ float sm[];
    float* Ks   = sm;
    float* Vs   = Ks + 64*68;
    float* Ps   = Vs + 64*68;
    float* rmax = Ps + 64*68;
    float* rsum = rmax + 256;

    int t  = threadIdx.x;
    int qt = blockIdx.x & 15;
    int h  = (blockIdx.x >> 4) & 31;
    int b  = blockIdx.x >> 9;
    int row = t >> 2;
    int eq  = t & 3;
    int qglob = qt*64 + row;

    float4 qv[16];
    const float* qp = g_qr + ((size_t)((b*SS + qglob)*HH + h))*HD;
#pragma unroll
    for (int u = 0; u < 16; u++) {
        float4 v = *(const float4*)(qp + 4*u);
        v.x *= 0.125f; v.y *= 0.125f; v.z *= 0.125f; v.w *= 0.125f;
        qv[u] = v;
    }

    float m = -INFINITY, l = 0.f;
    float4 O[4] = {make_float4(0,0,0,0), make_float4(0,0,0,0),
                   make_float4(0,0,0,0), make_float4(0,0,0,0)};

    for (int kt = 0; kt <= qt; kt++) {
        __syncthreads();
        {
            const float* kp = g_kr + ((size_t)((b*SS + kt*64 + row)*HH + h))*HD + eq*16;
            const float* vp = g_xv + ((size_t)((b*SS + kt*64 + row)*HH + h))*HD + eq*16;
#pragma unroll
            for (int u = 0; u < 4; u++) {
                *(float4*)&Ks[row*68 + eq*16 + 4*u] = *(const float4*)(kp + 4*u);
                *(float4*)&Vs[row*68 + eq*16 + 4*u] = *(const float4*)(vp + 4*u);
            }
        }
        __syncthreads();

        float lmax = -INFINITY;
#pragma unroll
        for (int j = 0; j < 16; j++) {
            int kc = eq*16 + j;
            float sv = 0.f;
#pragma unroll
            for (int u = 0; u < 16; u++) {
                float4 k4 = *(const float4*)&Ks[kc*68 + 4*u];
                sv += qv[u].x*k4.x + qv[u].y*k4.y + qv[u].z*k4.z + qv[u].w*k4.w;
            }
            if (kt == qt && kc > row) sv = -INFINITY;
            Ps[row*68 + kc] = sv;
            lmax = fmaxf(lmax, sv);
        }
        rmax[row*4 + eq] = lmax;
        __syncthreads();
        float tmax = fmaxf(fmaxf(rmax[row*4+0], rmax[row*4+1]),
                           fmaxf(rmax[row*4+2], rmax[row*4+3]));
        float mnew = fmaxf(m, tmax);
        float corr = __expf(m - mnew);
        float lsum = 0.f;
#pragma unroll
        for (int j = 0; j < 16; j++) {
            int kc = eq*16 + j;
            float p = __expf(Ps[row*68 + kc] - mnew);
            Ps[row*68 + kc] = p;
            lsum += p;
        }
        rsum[row*4 + eq] = lsum;
        __syncthreads();
        float tsum = rsum[row*4+0] + rsum[row*4+1] + rsum[row*4+2] + rsum[row*4+3];
        l = l * corr + tsum;
        m = mnew;
#pragma unroll
        for (int c = 0; c < 4; c++) {
            O[c].x *= corr; O[c].y *= corr; O[c].z *= corr; O[c].w *= corr;
        }
#pragma unroll 8
        for (int kc = 0; kc < 64; kc++) {
            float p = Ps[row*68 + kc];
#pragma unroll
            for (int c = 0; c < 4; c++) {
                float4 v4 = *(const float4*)&Vs[kc*68 + eq*4 + 16*c];
                O[c].x += p*v4.x; O[c].y += p*v4.y; O[c].z += p*v4.z; O[c].w += p*v4.w;
            }
        }
    }

    float gh = sigmf(gate[h]);
    float w1 = (1.f - gh) / l;
    float* op = g_comb + ((size_t)((b*SS + qglob)*HH + h))*HD;
#pragma unroll
    for (int c = 0; c < 4; c++) {
        int e = eq*4 + 16*c;
        float4 prev = *(const float4*)(op + e);
        float4 o;
        o.x = prev.x + w1*O[c].x;
        o.y = prev.y + w1*O[c].y;
        o.z = prev.z + w1*O[c].z;
        o.w = prev.w + w1*O[c].w;
        *(float4*)(op + e) = o;
    }
}

// ---------------- launcher ----------------
extern "C" void kernel_launch(void* const* d_in, const int* in_sizes, int n_in,
                              void* d_out, int out_size)
{
    const float* x     = (const float*)d_in[0];
    const float* pq    = (const float*)d_in[1];
    const float* ck    = (const float*)d_in[2];
    const float* cv    = (const float*)d_in[3];
    const float* meml  = (const float*)d_in[4];
    const float* memq  = (const float*)d_in[5];
    const float* nrm   = (const float*)d_in[6];
    const float* fc    = (const float*)d_in[7];
    const float* fs    = (const float*)d_in[8];
    const float* wq    = (const float*)d_in[10];
    const float* wk    = (const float*)d_in[11];
    const float* wv    = (const float*)d_in[12];
    const float* wo    = (const float*)d_in[13];
    const float* lq1   = (const float*)d_in[14];
    const float* lq2   = (const float*)d_in[15];
    const float* lk1   = (const float*)d_in[16];
    const float* lk2   = (const float*)d_in[17];
    const float* lv1   = (const float*)d_in[18];
    const float* lv2   = (const float*)d_in[19];
    const float* lo1   = (const float*)d_in[20];
    const float* lo2   = (const float*)d_in[21];
    const float* gate  = (const float*)d_in[22];
    const float* gw    = (const float*)d_in[23];
    const float* gb    = (const float*)d_in[24];
    float* out = (float*)d_out;

    fold_split_kernel<<<DIM, 256>>>(wq, lq1, lq2, 0);
    fold_split_kernel<<<DIM, 256>>>(wk, lk1, lk2, 1);
    fold_split_kernel<<<DIM, 256>>>(wv, lv1, lv2, 2);
    fold_split_kernel<<<DIM, 256>>>(wo, lo1, lo2, 3);

    split_x_kernel<<<(MM*DIM)/(256*8), 256>>>(x, 0);

    size_t gsm = NSTG * STG_BYTES;   // 92160 B
    cudaFuncSetAttribute(gemm_mma, cudaFuncAttributeMaxDynamicSharedMemorySize, (int)gsm);
    dim3 gg(DIM/128, MM/128);
    gemm_mma<<<gg, 256, gsm>>>(0, nullptr, 0);   // xq
    gemm_mma<<<gg, 256, gsm>>>(1, nullptr, 1);   // xk
    gemm_mma<<<gg, 256, gsm>>>(2, nullptr, 2);   // xv

    mem_stats_kernel<<<BB*HH, 256>>>(ck, cv, pq, meml, memq, nrm);
    mem_apply_kernel<<<BB*HH*(SS/32), 256>>>(gw, gb, gate);

    rope_kernel<<<(BB*SS*HH*32)/256, 256>>>(fc, fs);

    size_t fl_smem = (size_t)(3*64*68 + 512) * sizeof(float);
    cudaFuncSetAttribute(flash_kernel, cudaFuncAttributeMaxDynamicSharedMemorySize,
                         (int)fl_smem);
    flash_kernel<<<BB*HH*(SS/64), 256, fl_smem>>>(gate);

    split_x_kernel<<<(MM*DIM)/(256*8), 256>>>(nullptr, 1);
    gemm_mma<<<gg, 256, gsm>>>(3, out, 3);       // final projection
    (void)in_sizes; (void)n_in; (void)out_size;
}

// round 5
// speedup vs baseline: 4.2857x; 2.5613x over previous
#include <cuda_runtime.h>
#include <cuda_fp16.h>
#include <math.h>
#include <stdint.h>

// Problem constants
#define BB 4
#define SS 1024
#define DIM 2048
#define HH 32
#define HD 64
#define RR 16
#define MM (BB*SS)   // 4096

// ---------------- scratch (device globals; no allocation allowed) ----------------
__device__ __half g_whi[4][DIM*DIM];
__device__ __half g_wlo[4][DIM*DIM];
__device__ __half g_xhi[MM*DIM];
__device__ float g_xq[MM*DIM];
__device__ float g_xk[MM*DIM];
__device__ float g_xv[MM*DIM];
__device__ __half g_qh[MM*DIM];
__device__ __half g_ql[MM*DIM];
__device__ __half g_kh[MM*DIM];
__device__ __half g_vth[BB*HH*HD*SS];   // [bh][e][s] transposed V, fp16
__device__ float g_meml[BB*HH*HD*HD];
__device__ float g_memq[BB*HH*HD*HD];
__device__ float g_nrmt[BB*HH*HD];
__device__ float g_comb[MM*DIM];

__device__ __forceinline__ float elu1f(float x){ return x > 0.f ? x + 1.f : __expf(x); }
__device__ __forceinline__ float sigmf(float x){ return 1.f/(1.f+__expf(-x)); }

__device__ __forceinline__ uint32_t smem_u32(const void* p){
    uint32_t a;
    asm("{ .reg .u64 t; cvta.to.shared.u64 t, %1; cvt.u32.u64 %0, t; }" : "=r"(a) : "l"(p));
    return a;
}
__device__ __forceinline__ uint32_t pack2h(float x, float y){
    __half2 hh = __floats2half2_rn(x, y);
    return *(uint32_t*)&hh;
}

// ---------------- fp16 hi/lo split of 8 floats -> 2 uint4 ----------------
__device__ __forceinline__ void split8h(const float* v, uint4& hi, uint4& lo){
    unsigned h[4], l[4];
#pragma unroll
    for (int p = 0; p < 4; p++){
        __half h0 = __float2half_rn(v[2*p]);
        __half h1 = __float2half_rn(v[2*p+1]);
        __half l0 = __float2half_rn(v[2*p]   - __half2float(h0));
        __half l1 = __float2half_rn(v[2*p+1] - __half2float(h1));
        h[p] = (unsigned)__half_as_ushort(h0) | ((unsigned)__half_as_ushort(h1) << 16);
        l[p] = (unsigned)__half_as_ushort(l0) | ((unsigned)__half_as_ushort(l1) << 16);
    }
    hi = make_uint4(h[0], h[1], h[2], h[3]);
    lo = make_uint4(l[0], l[1], l[2], l[3]);
}

// ---------------- 1) fold LoRA into dense weights + fp16 split (fused x4) ------
struct FoldPtrs {
    const float* w[4];
    const float* l1[4];
    const float* l2[4];
};
__global__ __launch_bounds__(256)
void fold_split_all(FoldPtrs fp)
{
    int oi  = blockIdx.y;
    int row = blockIdx.x;
    int c0  = threadIdx.x * 8;
    const float* w  = fp.w[oi];
    const float* l1 = fp.l1[oi];
    const float* l2 = fp.l2[oi];
    float acc[8];
    const float4* wp = (const float4*)(w + (size_t)row*DIM + c0);
    float4 a = wp[0], b = wp[1];
    acc[0]=a.x; acc[1]=a.y; acc[2]=a.z; acc[3]=a.w;
    acc[4]=b.x; acc[5]=b.y; acc[6]=b.z; acc[7]=b.w;
#pragma unroll
    for (int r = 0; r < RR; r++){
        float s = __ldg(&l2[row*RR + r]);
        const float4* lp = (const float4*)(l1 + (size_t)r*DIM + c0);
        float4 u = lp[0], v = lp[1];
        acc[0]+=s*u.x; acc[1]+=s*u.y; acc[2]+=s*u.z; acc[3]+=s*u.w;
        acc[4]+=s*v.x; acc[5]+=s*v.y; acc[6]+=s*v.z; acc[7]+=s*v.w;
    }
    uint4 hi, lo; split8h(acc, hi, lo);
    *(uint4*)(&g_whi[oi][(size_t)row*DIM + c0]) = hi;
    *(uint4*)(&g_wlo[oi][(size_t)row*DIM + c0]) = lo;
}

// ---------------- 2) convert activations to fp16 (hi only) ----------------
__global__ __launch_bounds__(256)
void split_x_kernel(const float* __restrict__ src, int use_comb)
{
    size_t i = (size_t)(blockIdx.x*256 + threadIdx.x) * 8;
    const float* s = use_comb ? g_comb : src;
    const float4* p = (const float4*)(s + i);
    float4 a = p[0], b = p[1];
    unsigned h[4];
    h[0] = (unsigned)__half_as_ushort(__float2half_rn(a.x)) | ((unsigned)__half_as_ushort(__float2half_rn(a.y)) << 16);
    h[1] = (unsigned)__half_as_ushort(__float2half_rn(a.z)) | ((unsigned)__half_as_ushort(__float2half_rn(a.w)) << 16);
    h[2] = (unsigned)__half_as_ushort(__float2half_rn(b.x)) | ((unsigned)__half_as_ushort(__float2half_rn(b.y)) << 16);
    h[3] = (unsigned)__half_as_ushort(__float2half_rn(b.z)) | ((unsigned)__half_as_ushort(__float2half_rn(b.w)) << 16);
    *(uint4*)(&g_xhi[i]) = make_uint4(h[0], h[1], h[2], h[3]);
}

// ---------------- 3) HMMA 2-term GEMM (unchanged from R4) ----------------
#define KC 32
#define PITCH 40
#define SMAT (128*PITCH*2)
#define OFF_AH 0
#define OFF_BH SMAT
#define OFF_BL (2*SMAT)
#define STG_BYTES (3*SMAT)
#define NSTG 3
#define NCH (DIM/KC)

#define CP16(dst, src) asm volatile("cp.async.cg.shared.global [%0], [%1], 16;" :: "r"(dst), "l"(src))
#define CPCOMMIT()  asm volatile("cp.async.commit_group;" ::: "memory")
#define CPWAIT1()   asm volatile("cp.async.wait_group 1;" ::: "memory")
#define CPWAIT0()   asm volatile("cp.async.wait_group 0;" ::: "memory")
#define LDM4(r0,r1,r2,r3,addr) \
    asm volatile("ldmatrix.sync.aligned.m8n8.x4.shared.b16 {%0,%1,%2,%3}, [%4];" \
        : "=r"(r0), "=r"(r1), "=r"(r2), "=r"(r3) : "r"(addr))
#define MMA16816(c, a0,a1,a2,a3, b0,b1) \
    asm volatile("mma.sync.aligned.m16n8k16.row.col.f32.f16.f16.f32 " \
        "{%0,%1,%2,%3}, {%4,%5,%6,%7}, {%8,%9}, {%0,%1,%2,%3};" \
        : "+f"((c)[0]), "+f"((c)[1]), "+f"((c)[2]), "+f"((c)[3]) \
        : "r"(a0), "r"(a1), "r"(a2), "r"(a3), "r"(b0), "r"(b1))

__global__ __launch_bounds__(256, 2)
void gemm_mma(int widx, float* __restrict__ Yext, int ysel)
{
    extern __shared__ char dsm[];
    float* Y = (ysel==0) ? g_xq : (ysel==1) ? g_xk : (ysel==2) ? g_xv : Yext;
    const __half* Bhp = g_whi[widx];
    const __half* Blp = g_wlo[widx];

    int t = threadIdx.x, lane = t & 31, wid = t >> 5;
    int wm = wid >> 2, wn = wid & 3;
    int m0 = blockIdx.y * 128, n0 = blockIdx.x * 128;

    uint32_t sb0 = smem_u32(dsm);

    int pr = t >> 1, pc = (t & 1) * 16;
    const __half* gAh = g_xhi + (size_t)(m0 + pr)*DIM + pc;
    const __half* gBh = Bhp   + (size_t)(n0 + pr)*DIM + pc;
    const __half* gBl = Blp   + (size_t)(n0 + pr)*DIM + pc;
    uint32_t dA = sb0 + (uint32_t)((pr*PITCH + pc)*2);

    float acc[4][4][4];
#pragma unroll
    for (int i = 0; i < 4; i++)
#pragma unroll
        for (int j = 0; j < 4; j++)
#pragma unroll
            for (int k = 0; k < 4; k++) acc[i][j][k] = 0.f;

#pragma unroll
    for (int c = 0; c < 2; c++){
        uint32_t d = dA + c*STG_BYTES;
        int k0 = c*KC;
        CP16(d + OFF_AH, gAh + k0);  CP16(d + OFF_AH + 16, gAh + k0 + 8);
        CP16(d + OFF_BH, gBh + k0);  CP16(d + OFF_BH + 16, gBh + k0 + 8);
        CP16(d + OFF_BL, gBl + k0);  CP16(d + OFF_BL + 16, gBl + k0 + 8);
        CPCOMMIT();
    }

    int rsel = (lane & 15);
    int csel = (lane >> 4) * 8;
    int stg = 0, pstg = 2;

#pragma unroll 1
    for (int ch = 0; ch < NCH; ch++){
        if (ch == NCH - 1) { CPWAIT0(); } else { CPWAIT1(); }
        __syncthreads();

        if (ch + 2 < NCH){
            uint32_t d = dA + pstg*STG_BYTES;
            int k0 = (ch + 2)*KC;
            CP16(d + OFF_AH, gAh + k0);  CP16(d + OFF_AH + 16, gAh + k0 + 8);
            CP16(d + OFF_BH, gBh + k0);  CP16(d + OFF_BH + 16, gBh + k0 + 8);
            CP16(d + OFF_BL, gBl + k0);  CP16(d + OFF_BL + 16, gBl + k0 + 8);
            CPCOMMIT();
            pstg = (pstg == 2) ? 0 : pstg + 1;
        }

        uint32_t base = sb0 + stg*STG_BYTES;
        stg = (stg == 2) ? 0 : stg + 1;
#pragma unroll
        for (int ks = 0; ks < 2; ks++){
            int kofs = ks*16 + csel;
            uint32_t Bh[8], Bl[8];
#pragma unroll
            for (int p = 0; p < 2; p++){
                uint32_t ab = base + OFF_BH + (uint32_t)(((wn*32 + p*16 + rsel)*PITCH + kofs)*2);
                uint32_t r0,r1,r2,r3;
                LDM4(r0,r1,r2,r3, ab);
                Bh[4*p+0]=r0; Bh[4*p+1]=r2; Bh[4*p+2]=r1; Bh[4*p+3]=r3;
                LDM4(r0,r1,r2,r3, ab + (OFF_BL - OFF_BH));
                Bl[4*p+0]=r0; Bl[4*p+1]=r2; Bl[4*p+2]=r1; Bl[4*p+3]=r3;
            }
#pragma unroll
            for (int mt = 0; mt < 4; mt++){
                uint32_t aa = base + OFF_AH + (uint32_t)(((wm*64 + mt*16 + rsel)*PITCH + kofs)*2);
                uint32_t a0,a1,a2,a3;
                LDM4(a0,a1,a2,a3, aa);
#pragma unroll
                for (int nt = 0; nt < 4; nt++){
                    int p = nt >> 1, o = nt & 1;
                    MMA16816(acc[mt][nt], a0,a1,a2,a3, Bh[4*p + 2*o], Bh[4*p + 2*o + 1]);
                    MMA16816(acc[mt][nt], a0,a1,a2,a3, Bl[4*p + 2*o], Bl[4*p + 2*o + 1]);
                }
            }
        }
    }

    int grp = lane >> 2, tig = lane & 3;
#pragma unroll
    for (int mt = 0; mt < 4; mt++){
#pragma unroll
        for (int nt = 0; nt < 4; nt++){
            int r0 = m0 + wm*64 + mt*16 + grp;
            int c  = n0 + wn*32 + nt*8 + tig*2;
            *(float2*)&Y[(size_t)r0*DIM + c]       = make_float2(acc[mt][nt][0], acc[mt][nt][1]);
            *(float2*)&Y[(size_t)(r0+8)*DIM + c]   = make_float2(acc[mt][nt][2], acc[mt][nt][3]);
        }
    }
}

// ---------------- 4) memory-branch statistics per (b,h) ----------------
__global__ __launch_bounds__(256)
void mem_stats_kernel(const float* __restrict__ cache_k,
                      const float* __restrict__ cache_v,
                      const float* __restrict__ pquery,
                      const float* __restrict__ meml_in,
                      const float* __restrict__ memq_in,
                      const float* __restrict__ nrm_in)
{
    int bh = blockIdx.x;
    int b = bh >> 5, h = bh & 31;
    __shared__ float Ks[32][64];
    __shared__ float Vs[32][64];
    __shared__ float pqs[64];
    __shared__ float sig[32];

    int t = threadIdx.x;
    if (t < 64) pqs[t] = pquery[(b*HH + h)*HD + t];

    float accl[4][4] = {{0}}, accq[4][4] = {{0}};
    float accn = 0.f;
    int lrow = t >> 3;
    int lcol = (t & 7) * 8;
    int d0 = (t >> 4) * 4;
    int e0 = (t & 15) * 4;

    for (int s0 = 0; s0 < SS; s0 += 32) {
        __syncthreads();
        const float* kp = cache_k + ((size_t)((b*SS + s0 + lrow)*HH + h))*HD + lcol;
        const float* vp = cache_v + ((size_t)((b*SS + s0 + lrow)*HH + h))*HD + lcol;
        *(float4*)&Ks[lrow][lcol]   = *(const float4*)kp;
        *(float4*)&Ks[lrow][lcol+4] = *(const float4*)(kp + 4);
        *(float4*)&Vs[lrow][lcol]   = *(const float4*)vp;
        *(float4*)&Vs[lrow][lcol+4] = *(const float4*)(vp + 4);
        __syncthreads();
        if (t < 32) {
            float sum = 0.f;
#pragma unroll
            for (int d = 0; d < 64; d++) sum += pqs[d] * Ks[t][d];
            sig[t] = sigmf(sum * 0.125f);
        }
        __syncthreads();
#pragma unroll
        for (int u = 0; u < 8; u++) Ks[lrow][lcol+u] = elu1f(Ks[lrow][lcol+u]);
        __syncthreads();
        if (t < 64) {
#pragma unroll
            for (int s = 0; s < 32; s++) accn += Ks[s][t];
        }
#pragma unroll 4
        for (int s = 0; s < 32; s++) {
            float4 k4 = *(const float4*)&Ks[s][d0];
            float4 v4 = *(const float4*)&Vs[s][e0];
            float sg = sig[s];
            float ka[4] = {k4.x, k4.y, k4.z, k4.w};
            float kb[4] = {k4.x*sg, k4.y*sg, k4.z*sg, k4.w*sg};
            float vv[4] = {v4.x, v4.y, v4.z, v4.w};
#pragma unroll
            for (int i = 0; i < 4; i++)
#pragma unroll
                for (int j = 0; j < 4; j++) {
                    accl[i][j] += ka[i] * vv[j];
                    accq[i][j] += kb[i] * vv[j];
                }
        }
    }
    size_t base = (size_t)bh * HD * HD;
#pragma unroll
    for (int i = 0; i < 4; i++)
#pragma unroll
        for (int j = 0; j < 4; j++) {
            size_t idx = base + (size_t)(d0 + i)*HD + (e0 + j);
            g_meml[idx] = meml_in[idx] + accl[i][j];
            g_memq[idx] = memq_in[idx] + accq[i][j];
        }
    if (t < 64) g_nrmt[bh*HD + t] = nrm_in[bh*HD + t] + accn;
}

// ---------------- 5) memory-branch apply: g * mem_comb -> g_comb ----------------
__global__ __launch_bounds__(256)
void mem_apply_kernel(const float* __restrict__ gmem_w,
                      const float* __restrict__ gmem_b,
                      const float* __restrict__ gate)
{
    int idx = blockIdx.x;
    int st = idx & 31;
    int h  = (idx >> 5) & 31;
    int b  = idx >> 10;
    int bh = b*HH + h;
    int s0 = st * 32;

    __shared__ float ml[64*64];
    __shared__ float mq[64*64];
    __shared__ float sq[32*68];
    __shared__ float nrm[64];
    __shared__ float wv[64];
    __shared__ float gpart[32*8];

    int t = threadIdx.x;
    {
        int r = t >> 2, c = (t & 3) * 16;
        size_t gbase = (size_t)bh*HD*HD + (size_t)r*HD + c;
#pragma unroll
        for (int u = 0; u < 4; u++) {
            *(float4*)&ml[r*64 + c + 4*u] = *(const float4*)&g_meml[gbase + 4*u];
            *(float4*)&mq[r*64 + c + 4*u] = *(const float4*)&g_memq[gbase + 4*u];
        }
    }
    {
        int r = t >> 3, c = (t & 7) * 8;
        const float* xp = g_xq + ((size_t)((b*SS + s0 + r)*HH + h))*HD + c;
        float4 a = *(const float4*)xp;
        float4 bv = *(const float4*)(xp + 4);
        float4 ea = make_float4(elu1f(a.x), elu1f(a.y), elu1f(a.z), elu1f(a.w));
        float4 eb = make_float4(elu1f(bv.x), elu1f(bv.y), elu1f(bv.z), elu1f(bv.w));
        *(float4*)&sq[r*68 + c]     = ea;
        *(float4*)&sq[r*68 + c + 4] = eb;
    }
    if (t < 64) { nrm[t] = g_nrmt[bh*HD + t]; wv[t] = gmem_w[t]; }
    __syncthreads();

    int row = t >> 3;
    int eq  = t & 7;
    float denom = 0.f;
#pragma unroll
    for (int d = 0; d < 64; d++) denom += sq[row*68 + d] * nrm[d];

    float4 mo[2]  = {make_float4(0,0,0,0), make_float4(0,0,0,0)};
    float4 qmo[2] = {make_float4(0,0,0,0), make_float4(0,0,0,0)};
#pragma unroll
    for (int d = 0; d < 64; d++) {
        float sd = sq[row*68 + d];
#pragma unroll
        for (int c = 0; c < 2; c++) {
            float4 m4 = *(const float4*)&ml[d*64 + eq*4 + 32*c];
            float4 q4 = *(const float4*)&mq[d*64 + eq*4 + 32*c];
            mo[c].x += sd*m4.x; mo[c].y += sd*m4.y; mo[c].z += sd*m4.z; mo[c].w += sd*m4.w;
            qmo[c].x += sd*q4.x; qmo[c].y += sd*q4.y; qmo[c].z += sd*q4.z; qmo[c].w += sd*q4.w;
        }
    }
    float inv = 1.f / denom;
    float gp = 0.f;
#pragma unroll
    for (int c = 0; c < 2; c++) {
        mo[c].x *= inv; mo[c].y *= inv; mo[c].z *= inv; mo[c].w *= inv;
        qmo[c].x *= inv; qmo[c].y *= inv; qmo[c].z *= inv; qmo[c].w *= inv;
        int e = eq*4 + 32*c;
        gp += qmo[c].x*wv[e] + qmo[c].y*wv[e+1] + qmo[c].z*wv[e+2] + qmo[c].w*wv[e+3];
    }
    gpart[row*8 + eq] = gp;
    __syncthreads();
    float gsum = 0.f;
#pragma unroll
    for (int i = 0; i < 8; i++) gsum += gpart[row*8 + i];
    float gq = sigmf(gsum + gmem_b[0]);
    float gh = sigmf(gate[h]);

    float* op = g_comb + ((size_t)((b*SS + s0 + row)*HH + h))*HD;
#pragma unroll
    for (int c = 0; c < 2; c++) {
        float4 o;
        o.x = gh * (mo[c].x + gq*qmo[c].x);
        o.y = gh * (mo[c].y + gq*qmo[c].y);
        o.z = gh * (mo[c].z + gq*qmo[c].z);
        o.w = gh * (mo[c].w + gq*qmo[c].w);
        *(float4*)(op + eq*4 + 32*c) = o;
    }
}

// ---------------- 6) RoPE -> fp16 (q split hi/lo pre-scaled, k hi) ----------------
__global__ void rope_kernel(const float* __restrict__ fc, const float* __restrict__ fs)
{
    int idx = blockIdx.x * 256 + threadIdx.x;
    int i = idx & 31;
    int s = (idx >> 10) & 1023;
    size_t pos = (size_t)idx * 2;
    float c = fc[s*32 + i];
    float sn = fs[s*32 + i];
    float a = g_xq[pos], b2 = g_xq[pos+1];
    float q0 = (a*c - b2*sn) * 0.125f;
    float q1 = (a*sn + b2*c) * 0.125f;
    __half h0 = __float2half_rn(q0), h1 = __float2half_rn(q1);
    *(__half2*)&g_qh[pos] = __halves2half2(h0, h1);
    *(__half2*)&g_ql[pos] = __halves2half2(__float2half_rn(q0 - __half2float(h0)),
                                           __float2half_rn(q1 - __half2float(h1)));
    a = g_xk[pos]; b2 = g_xk[pos+1];
    *(__half2*)&g_kh[pos] = __halves2half2(__float2half_rn(a*c - b2*sn),
                                           __float2half_rn(a*sn + b2*c));
}

// ---------------- 7) transpose V -> g_vth [bh][e][s] fp16 ----------------
__global__ __launch_bounds__(256)
void v_trans_kernel()
{
    __shared__ __half sm[64*68];
    int bh = blockIdx.x & 127;
    int st = blockIdx.x >> 7;
    int b = bh >> 5, h = bh & 31;
    int s0 = st * 64;
    int t = threadIdx.x;

    {   // load 64x64 fp32 V, convert, store to smem
        int sl = t >> 2, e0 = (t & 3) * 16;
        const float* vp = g_xv + ((size_t)((b*SS + s0 + sl)*HH + h))*HD + e0;
#pragma unroll
        for (int u = 0; u < 4; u++){
            float4 v = *(const float4*)(vp + 4*u);
            __half2 p0 = __floats2half2_rn(v.x, v.y);
            __half2 p1 = __floats2half2_rn(v.z, v.w);
            *(__half2*)&sm[sl*68 + e0 + 4*u]     = p0;
            *(__half2*)&sm[sl*68 + e0 + 4*u + 2] = p1;
        }
    }
    __syncthreads();
    {   // write transposed
        int el = t >> 2, sb = (t & 3) * 16;
        __half hv[16];
#pragma unroll
        for (int j = 0; j < 16; j++) hv[j] = sm[(sb + j)*68 + el];
        __half* dst = g_vth + ((size_t)(bh*HD + el))*SS + s0 + sb;
        *(uint4*)dst       = *(uint4*)&hv[0];
        *(uint4*)(dst + 8) = *(uint4*)&hv[8];
    }
}

// ---------------- 8) HMMA flash attention + combine ----------------
#define PF 72                       // halves per smem row (144B pitch, conflict-free)
#define FQH 0
#define FQL (64*PF)
#define FST0 (2*64*PF)              // stage s: K at FST0 + s*2*64*PF, V right after K

__device__ __forceinline__ void flash_load_kv(uint32_t skb, int t, int bh, int b, int h, int kt)
{
    int r = t >> 1, c0 = (t & 1) * 32;
    const __half* ks = g_kh + ((size_t)((b*SS + kt*64 + r)*HH + h))*HD + c0;
    const __half* vs = g_vth + ((size_t)(bh*HD + r))*SS + kt*64 + c0;
    uint32_t dk = skb + (uint32_t)((r*PF + c0)*2);
    uint32_t dv = dk + 64*PF*2;
    CP16(dk, ks); CP16(dk+16, ks+8); CP16(dk+32, ks+16); CP16(dk+48, ks+24);
    CP16(dv, vs); CP16(dv+16, vs+8); CP16(dv+32, vs+16); CP16(dv+48, vs+24);
}

__global__ __launch_bounds__(128)
void flash_mma(const float* __restrict__ gate)
{
    extern __shared__ __half fsm[];
    int t = threadIdx.x, lane = t & 31, wid = t >> 5;
    int qt = blockIdx.x & 15;
    int h  = (blockIdx.x >> 4) & 31;
    int b  = blockIdx.x >> 9;
    int bh = b*HH + h;
    uint32_t sb = smem_u32(fsm);

    // stage Q (hi and lo)
    {
        int r = t >> 1, c0 = (t & 1) * 32;
        const __half* qsh = g_qh + ((size_t)((b*SS + qt*64 + r)*HH + h))*HD + c0;
        const __half* qsl = g_ql + ((size_t)((b*SS + qt*64 + r)*HH + h))*HD + c0;
        uint32_t dh = sb + (uint32_t)((r*PF + c0)*2);
        uint32_t dl = dh + FQL*2;
        CP16(dh, qsh); CP16(dh+16, qsh+8); CP16(dh+32, qsh+16); CP16(dh+48, qsh+24);
        CP16(dl, qsl); CP16(dl+16, qsl+8); CP16(dl+32, qsl+16); CP16(dl+48, qsl+24);
        CPCOMMIT();
    }
    // prefetch kt=0
    flash_load_kv(sb + FST0*2, t, bh, b, h, 0);
    CPCOMMIT();

    // Q fragments (after Q group done; kt=0 group may still be pending)
    CPWAIT1();
    __syncthreads();
    int rsel = lane & 15, csel = (lane >> 4) * 8;
    uint32_t qh[4][4], ql[4][4];
#pragma unroll
    for (int ks = 0; ks < 4; ks++){
        uint32_t a = sb + (uint32_t)(((wid*16 + rsel)*PF + ks*16 + csel)*2);
        LDM4(qh[ks][0], qh[ks][1], qh[ks][2], qh[ks][3], a);
        LDM4(ql[ks][0], ql[ks][1], ql[ks][2], ql[ks][3], a + FQL*2);
    }

    float m0 = -1e30f, m1 = -1e30f, l0 = 0.f, l1 = 0.f;
    float O[8][4];
#pragma unroll
    for (int j = 0; j < 8; j++)
#pragma unroll
        for (int r = 0; r < 4; r++) O[j][r] = 0.f;

    int g  = lane >> 2, t2 = lane & 3;

#pragma unroll 1
    for (int kt = 0; kt <= qt; kt++){
        CPWAIT0();
        __syncthreads();
        if (kt < qt){
            flash_load_kv(sb + (FST0 + ((kt+1)&1)*2*64*PF)*2, t, bh, b, h, kt+1);
            CPCOMMIT();
        }
        uint32_t kbase = sb + (uint32_t)((FST0 + (kt&1)*2*64*PF)*2);
        uint32_t vbase = kbase + 64*PF*2;

        // ---- S = (Qh+Ql) · Kh^T ----
        float sacc[8][4];
#pragma unroll
        for (int j = 0; j < 8; j++)
#pragma unroll
            for (int r = 0; r < 4; r++) sacc[j][r] = 0.f;
#pragma unroll
        for (int ks = 0; ks < 4; ks++){
#pragma unroll
            for (int nb = 0; nb < 4; nb++){
                uint32_t r0,r1,r2,r3;
                LDM4(r0,r1,r2,r3, kbase + (uint32_t)(((nb*16 + rsel)*PF + ks*16 + csel)*2));
                MMA16816(sacc[2*nb],   qh[ks][0],qh[ks][1],qh[ks][2],qh[ks][3], r0, r2);
                MMA16816(sacc[2*nb],   ql[ks][0],ql[ks][1],ql[ks][2],ql[ks][3], r0, r2);
                MMA16816(sacc[2*nb+1], qh[ks][0],qh[ks][1],qh[ks][2],qh[ks][3], r1, r3);
                MMA16816(sacc[2*nb+1], ql[ks][0],ql[ks][1],ql[ks][2],ql[ks][3], r1, r3);
            }
        }
        // causal mask on diagonal tile
        if (kt == qt){
            int ml0 = wid*16 + g, ml1 = ml0 + 8;
#pragma unroll
            for (int j = 0; j < 8; j++){
                int n0 = j*8 + t2*2, n1 = n0 + 1;
                if (n0 > ml0) sacc[j][0] = -1e30f;
                if (n1 > ml0) sacc[j][1] = -1e30f;
                if (n0 > ml1) sacc[j][2] = -1e30f;
                if (n1 > ml1) sacc[j][3] = -1e30f;
            }
        }
        // row max
        float vx0 = -1e30f, vx1 = -1e30f;
#pragma unroll
        for (int j = 0; j < 8; j++){
            vx0 = fmaxf(vx0, fmaxf(sacc[j][0], sacc[j][1]));
            vx1 = fmaxf(vx1, fmaxf(sacc[j][2], sacc[j][3]));
        }
        vx0 = fmaxf(vx0, __shfl_xor_sync(0xffffffffu, vx0, 1));
        vx0 = fmaxf(vx0, __shfl_xor_sync(0xffffffffu, vx0, 2));
        vx1 = fmaxf(vx1, __shfl_xor_sync(0xffffffffu, vx1, 1));
        vx1 = fmaxf(vx1, __shfl_xor_sync(0xffffffffu, vx1, 2));
        float n0f = fmaxf(m0, vx0), n1f = fmaxf(m1, vx1);
        float c0f = __expf(m0 - n0f), c1f = __expf(m1 - n1f);
        m0 = n0f; m1 = n1f;
        // P = exp(S - m), row sums (in place)
        float s0 = 0.f, s1 = 0.f;
#pragma unroll
        for (int j = 0; j < 8; j++){
            sacc[j][0] = __expf(sacc[j][0] - n0f);
            sacc[j][1] = __expf(sacc[j][1] - n0f);
            sacc[j][2] = __expf(sacc[j][2] - n1f);
            sacc[j][3] = __expf(sacc[j][3] - n1f);
            s0 += sacc[j][0] + sacc[j][1];
            s1 += sacc[j][2] + sacc[j][3];
        }
        s0 += __shfl_xor_sync(0xffffffffu, s0, 1);
        s0 += __shfl_xor_sync(0xffffffffu, s0, 2);
        s1 += __shfl_xor_sync(0xffffffffu, s1, 1);
        s1 += __shfl_xor_sync(0xffffffffu, s1, 2);
        l0 = l0*c0f + s0;
        l1 = l1*c1f + s1;
        // rescale O
#pragma unroll
        for (int j = 0; j < 8; j++){
            O[j][0] *= c0f; O[j][1] *= c0f;
            O[j][2] *= c1f; O[j][3] *= c1f;
        }
        // P fragments (fp16)
        uint32_t pa[4][4];
#pragma unroll
        for (int ks = 0; ks < 4; ks++){
            pa[ks][0] = pack2h(sacc[2*ks][0],   sacc[2*ks][1]);
            pa[ks][1] = pack2h(sacc[2*ks][2],   sacc[2*ks][3]);
            pa[ks][2] = pack2h(sacc[2*ks+1][0], sacc[2*ks+1][1]);
            pa[ks][3] = pack2h(sacc[2*ks+1][2], sacc[2*ks+1][3]);
        }
        // ---- O += P · V  (V^T tiles: rows = hd, cols = keys) ----
#pragma unroll
        for (int ks = 0; ks < 4; ks++){
#pragma unroll
            for (int nb = 0; nb < 4; nb++){
                uint32_t r0,r1,r2,r3;
                LDM4(r0,r1,r2,r3, vbase + (uint32_t)(((nb*16 + rsel)*PF + ks*16 + csel)*2));
                MMA16816(O[2*nb],   pa[ks][0],pa[ks][1],pa[ks][2],pa[ks][3], r0, r2);
                MMA16816(O[2*nb+1], pa[ks][0],pa[ks][1],pa[ks][2],pa[ks][3], r1, r3);
            }
        }
    }

    float gh_ = sigmf(gate[h]);
    float w0 = (1.f - gh_) / l0;
    float w1 = (1.f - gh_) / l1;
    size_t row0 = ((size_t)((b*SS + qt*64 + wid*16 + g)*HH + h))*HD;
    size_t row1 = row0 + (size_t)8*HH*HD;
#pragma unroll
    for (int j = 0; j < 8; j++){
        int c = j*8 + t2*2;
        float2 p0 = *(float2*)&g_comb[row0 + c];
        p0.x += w0*O[j][0]; p0.y += w0*O[j][1];
        *(float2*)&g_comb[row0 + c] = p0;
        float2 p1 = *(float2*)&g_comb[row1 + c];
        p1.x += w1*O[j][2]; p1.y += w1*O[j][3];
        *(float2*)&g_comb[row1 + c] = p1;
    }
}

// ---------------- launcher ----------------
extern "C" void kernel_launch(void* const* d_in, const int* in_sizes, int n_in,
                              void* d_out, int out_size)
{
    const float* x     = (const float*)d_in[0];
    const float* pq    = (const float*)d_in[1];
    const float* ck    = (const float*)d_in[2];
    const float* cv    = (const float*)d_in[3];
    const float* meml  = (const float*)d_in[4];
    const float* memq  = (const float*)d_in[5];
    const float* nrm   = (const float*)d_in[6];
    const float* fc    = (const float*)d_in[7];
    const float* fs    = (const float*)d_in[8];
    const float* wq    = (const float*)d_in[10];
    const float* wk    = (const float*)d_in[11];
    const float* wv    = (const float*)d_in[12];
    const float* wo    = (const float*)d_in[13];
    const float* lq1   = (const float*)d_in[14];
    const float* lq2   = (const float*)d_in[15];
    const float* lk1   = (const float*)d_in[16];
    const float* lk2   = (const float*)d_in[17];
    const float* lv1   = (const float*)d_in[18];
    const float* lv2   = (const float*)d_in[19];
    const float* lo1   = (const float*)d_in[20];
    const float* lo2   = (const float*)d_in[21];
    const float* gate  = (const float*)d_in[22];
    const float* gw    = (const float*)d_in[23];
    const float* gb    = (const float*)d_in[24];
    float* out = (float*)d_out;

    FoldPtrs fp;
    fp.w[0] = wq; fp.w[1] = wk; fp.w[2] = wv; fp.w[3] = wo;
    fp.l1[0] = lq1; fp.l1[1] = lk1; fp.l1[2] = lv1; fp.l1[3] = lo1;
    fp.l2[0] = lq2; fp.l2[1] = lk2; fp.l2[2] = lv2; fp.l2[3] = lo2;
    fold_split_all<<<dim3(DIM, 4), 256>>>(fp);

    split_x_kernel<<<(MM*DIM)/(256*8), 256>>>(x, 0);

    size_t gsm = NSTG * STG_BYTES;
    cudaFuncSetAttribute(gemm_mma, cudaFuncAttributeMaxDynamicSharedMemorySize, (int)gsm);
    dim3 gg(DIM/128, MM/128);
    gemm_mma<<<gg, 256, gsm>>>(0, nullptr, 0);   // xq
    gemm_mma<<<gg, 256, gsm>>>(1, nullptr, 1);   // xk
    gemm_mma<<<gg, 256, gsm>>>(2, nullptr, 2);   // xv

    mem_stats_kernel<<<BB*HH, 256>>>(ck, cv, pq, meml, memq, nrm);
    mem_apply_kernel<<<BB*HH*(SS/32), 256>>>(gw, gb, gate);

    rope_kernel<<<(BB*SS*HH*32)/256, 256>>>(fc, fs);
    v_trans_kernel<<<BB*HH*(SS/64), 256>>>();

    size_t fsmem = (size_t)(6*64*PF) * sizeof(__half);  // 55296 B
    cudaFuncSetAttribute(flash_mma, cudaFuncAttributeMaxDynamicSharedMemorySize, (int)fsmem);
    flash_mma<<<BB*HH*(SS/64), 128, fsmem>>>(gate);

    split_x_kernel<<<(MM*DIM)/(256*8), 256>>>(nullptr, 1);
    gemm_mma<<<gg, 256, gsm>>>(3, out, 3);       // final projection
    (void)in_sizes; (void)n_in; (void)out_size;
}